// round 3
// baseline (speedup 1.0000x reference)
#include <cuda_runtime.h>
#include <cuda_bf16.h>
#include <cstdint>

#define NNODES 50000
#define NEDGES 500000
#define ETOT   550000     // edges + self loops
#define HCDIM  128        // heads*hid for layers 0-2
#define OUTC   16

// -------- scratch (no cudaMalloc allowed) --------
__device__ __align__(16) float g_h1[(size_t)NNODES * HCDIM];
__device__ __align__(16) float g_h2[(size_t)NNODES * HCDIM];
__device__ __align__(16) float g_xl[(size_t)NNODES * HCDIM];
__device__ __align__(16) float g_xr[(size_t)NNODES * HCDIM];
__device__ int   g_srcbuf[ETOT];
__device__ int   g_seg[NNODES + 1];
__device__ int   g_hist[NNODES];
__device__ int   g_cursor[NNODES];

__device__ __forceinline__ float* bufptr(int id) {
    switch (id) {
        case 0: return g_xl;
        case 1: return g_xr;
        case 2: return g_h1;
        default: return g_h2;
    }
}

__device__ __forceinline__ float lrelu(float v) { return v > 0.f ? v : 0.2f * v; }
__device__ __forceinline__ float elu1(float v)  { return v > 0.f ? v : expm1f(v); }

// -------- edge preprocessing: counting sort by dst --------
__global__ void zero_hist_kernel() {
    int i = blockIdx.x * blockDim.x + threadIdx.x;
    if (i < NNODES) g_hist[i] = 0;
}

// edge_index is int32 (JAX x64 disabled downgrades int64 -> int32)
__global__ void hist_kernel(const int* __restrict__ ei) {
    int i = blockIdx.x * blockDim.x + threadIdx.x;
    if (i >= ETOT) return;
    int d = (i < NEDGES) ? ei[NEDGES + i] : (i - NEDGES);
    atomicAdd(&g_hist[d], 1);
}

__global__ void scan_kernel() {
    __shared__ int wsum[32];
    int t = threadIdx.x;
    int lane = t & 31, wid = t >> 5;
    int offset = 0;
    for (int base = 0; base < NNODES; base += 1024) {
        int i = base + t;
        int v = (i < NNODES) ? g_hist[i] : 0;
        int x = v;
#pragma unroll
        for (int d = 1; d < 32; d <<= 1) {
            int y = __shfl_up_sync(0xffffffffu, x, d);
            if (lane >= d) x += y;
        }
        if (lane == 31) wsum[wid] = x;
        __syncthreads();
        if (wid == 0) {
            int w = wsum[lane];
#pragma unroll
            for (int d = 1; d < 32; d <<= 1) {
                int y = __shfl_up_sync(0xffffffffu, w, d);
                if (lane >= d) w += y;
            }
            wsum[lane] = w;
        }
        __syncthreads();
        int incl = x + (wid ? wsum[wid - 1] : 0);
        if (i < NNODES) {
            int excl = offset + incl - v;
            g_seg[i] = excl;
            g_cursor[i] = excl;
        }
        offset += wsum[31];
        __syncthreads();
    }
    if (t == 0) g_seg[NNODES] = offset;
}

__global__ void scatter_kernel(const int* __restrict__ ei) {
    int i = blockIdx.x * blockDim.x + threadIdx.x;
    if (i >= ETOT) return;
    int s, d;
    if (i < NEDGES) { s = ei[i]; d = ei[NEDGES + i]; }
    else            { s = d = i - NEDGES; }
    int p = atomicAdd(&g_cursor[d], 1);
    g_srcbuf[p] = s;
}

// -------- fp32 register-tiled SGEMM: C[M,Nn] = A[M,K] @ B[K,Nn] --------
template <int BM, int BN, int BK, int TM, int TN>
__global__ void sgemm_kernel(const float* __restrict__ Aext, int aid, int cid,
                             const float* __restrict__ B, int M, int Nn, int K) {
    constexpr int TX = BN / TN;   // threads in N dir
    constexpr int TY = BM / TM;   // threads in M dir
    constexpr int NT = TX * TY;   // total threads (256)
    __shared__ float As[BK][BM];
    __shared__ float Bs[BK][BN + 4];

    const float* A = (aid < 0) ? Aext : bufptr(aid);
    float* C = bufptr(cid);

    int t = threadIdx.x;
    int tx = t % TX, ty = t / TX;
    int mBase = blockIdx.x * BM;
    int nBase = blockIdx.y * BN;

    float acc[TM][TN];
#pragma unroll
    for (int i = 0; i < TM; i++)
#pragma unroll
        for (int j = 0; j < TN; j++) acc[i][j] = 0.f;

    for (int kk = 0; kk < K; kk += BK) {
        // load A tile BM x BK (transposed into As[k][m])
        for (int i = t; i < BM * BK; i += NT) {
            int m = i / BK, k = i % BK;
            int gm = mBase + m;
            As[k][m] = (gm < M) ? A[(size_t)gm * K + kk + k] : 0.f;
        }
        // load B tile BK x BN
        for (int i = t; i < BK * BN; i += NT) {
            int k = i / BN, n = i % BN;
            Bs[k][n] = B[(size_t)(kk + k) * Nn + nBase + n];
        }
        __syncthreads();
#pragma unroll
        for (int k = 0; k < BK; k++) {
            float a[TM], b[TN];
#pragma unroll
            for (int i = 0; i < TM; i++) a[i] = As[k][ty + TY * i];
#pragma unroll
            for (int j = 0; j < TN; j++) b[j] = Bs[k][tx + TX * j];
#pragma unroll
            for (int i = 0; i < TM; i++)
#pragma unroll
                for (int j = 0; j < TN; j++)
                    acc[i][j] = fmaf(a[i], b[j], acc[i][j]);
        }
        __syncthreads();
    }
#pragma unroll
    for (int i = 0; i < TM; i++) {
        int gm = mBase + ty + TY * i;
        if (gm >= M) continue;
#pragma unroll
        for (int j = 0; j < TN; j++) {
            int gn = nBase + tx + TX * j;
            C[(size_t)gm * Nn + gn] = acc[i][j];
        }
    }
}

// -------- edge pass, layers 0-2: softmax-aggregate + bias + BN + ELU fused --------
// One warp per destination node; lane owns 4 channels; head = lane/4.
__global__ void edge_full_kernel(const float* __restrict__ att,
                                 const float* __restrict__ bias,
                                 const float* __restrict__ bg,
                                 const float* __restrict__ bb,
                                 const float* __restrict__ bm,
                                 const float* __restrict__ bv,
                                 int outid) {
    int gw = (blockIdx.x * blockDim.x + threadIdx.x) >> 5;
    if (gw >= NNODES) return;
    int lane = threadIdx.x & 31;
    int n = gw;
    int c0 = lane * 4;

    const float4 xrv = *(const float4*)(g_xr + (size_t)n * HCDIM + c0);
    const float4 av  = *(const float4*)(att + c0);

    int beg = g_seg[n], end = g_seg[n + 1];
    float acc0 = 0.f, acc1 = 0.f, acc2 = 0.f, acc3 = 0.f, den = 0.f;

    for (int e = beg; e < end; e += 2) {
        int s0 = g_srcbuf[e];
        bool two = (e + 1 < end);
        int s1 = two ? g_srcbuf[e + 1] : s0;
        float4 x0 = *(const float4*)(g_xl + (size_t)s0 * HCDIM + c0);
        float4 x1 = *(const float4*)(g_xl + (size_t)s1 * HCDIM + c0);
        {
            float p = lrelu(x0.x + xrv.x) * av.x + lrelu(x0.y + xrv.y) * av.y
                    + lrelu(x0.z + xrv.z) * av.z + lrelu(x0.w + xrv.w) * av.w;
            p += __shfl_xor_sync(0xffffffffu, p, 1);
            p += __shfl_xor_sync(0xffffffffu, p, 2);
            float aE = __expf(p);   // max-subtraction skipped: |logit| ~ O(1)
            den += aE;
            acc0 = fmaf(x0.x, aE, acc0); acc1 = fmaf(x0.y, aE, acc1);
            acc2 = fmaf(x0.z, aE, acc2); acc3 = fmaf(x0.w, aE, acc3);
        }
        {
            float p = lrelu(x1.x + xrv.x) * av.x + lrelu(x1.y + xrv.y) * av.y
                    + lrelu(x1.z + xrv.z) * av.z + lrelu(x1.w + xrv.w) * av.w;
            p += __shfl_xor_sync(0xffffffffu, p, 1);
            p += __shfl_xor_sync(0xffffffffu, p, 2);
            float aE = two ? __expf(p) : 0.f;
            den += aE;
            acc0 = fmaf(x1.x, aE, acc0); acc1 = fmaf(x1.y, aE, acc1);
            acc2 = fmaf(x1.z, aE, acc2); acc3 = fmaf(x1.w, aE, acc3);
        }
    }

    float inv = 1.f / den;   // self-loop guarantees den > 0
    float4 bi  = *(const float4*)(bias + c0);
    float4 gg  = *(const float4*)(bg + c0);
    float4 bev = *(const float4*)(bb + c0);
    float4 mm  = *(const float4*)(bm + c0);
    float4 vv  = *(const float4*)(bv + c0);

    float4 r;
    r.x = elu1((acc0 * inv + bi.x - mm.x) * rsqrtf(vv.x + 1e-5f) * gg.x + bev.x);
    r.y = elu1((acc1 * inv + bi.y - mm.y) * rsqrtf(vv.y + 1e-5f) * gg.y + bev.y);
    r.z = elu1((acc2 * inv + bi.z - mm.z) * rsqrtf(vv.z + 1e-5f) * gg.z + bev.z);
    r.w = elu1((acc3 * inv + bi.w - mm.w) * rsqrtf(vv.w + 1e-5f) * gg.w + bev.w);

    float* out = bufptr(outid);
    *(float4*)(out + (size_t)n * HCDIM + c0) = r;
}

// -------- edge pass, layer 3 (1 head, 16 channels) -> d_out --------
// Warp = node; 2 half-warps process alternating edges; channel = lane&15.
__global__ void edge_out_kernel(const float* __restrict__ att,
                                const float* __restrict__ bias,
                                float* __restrict__ out) {
    int gw = (blockIdx.x * blockDim.x + threadIdx.x) >> 5;
    if (gw >= NNODES) return;
    int lane = threadIdx.x & 31;
    int c = lane & 15;
    int half = lane >> 4;
    int n = gw;

    float xrv = g_xr[(size_t)n * OUTC + c];
    float av  = att[c];
    int beg = g_seg[n], end = g_seg[n + 1];
    float acc = 0.f, den = 0.f;
    int iters = (end - beg + 1) >> 1;
    for (int i = 0; i < iters; i++) {
        int e = beg + 2 * i + half;
        bool valid = (e < end);
        int s = valid ? g_srcbuf[e] : g_srcbuf[beg];
        float xlv = g_xl[(size_t)s * OUTC + c];
        float p = lrelu(xlv + xrv) * av;
        p += __shfl_xor_sync(0xffffffffu, p, 1);
        p += __shfl_xor_sync(0xffffffffu, p, 2);
        p += __shfl_xor_sync(0xffffffffu, p, 4);
        p += __shfl_xor_sync(0xffffffffu, p, 8);
        float aE = valid ? __expf(p) : 0.f;
        den += aE;
        acc = fmaf(xlv, aE, acc);
    }
    acc += __shfl_xor_sync(0xffffffffu, acc, 16);
    den += __shfl_xor_sync(0xffffffffu, den, 16);
    if (half == 0) out[(size_t)n * OUTC + c] = acc / den + bias[c];
}

// -------- orchestration --------
extern "C" void kernel_launch(void* const* d_in, const int* in_sizes, int n_in,
                              void* d_out, int out_size) {
    const float* x  = (const float*)d_in[0];
    const int*   ei = (const int*)d_in[1];   // int32 (JAX default x64 disabled)
    // layer params: W{i}l, W{i}r, a{i}, b{i} at 2+4i..5+4i
    const float* W0l = (const float*)d_in[2];
    const float* W0r = (const float*)d_in[3];
    const float* a0  = (const float*)d_in[4];
    const float* b0  = (const float*)d_in[5];
    const float* W1l = (const float*)d_in[6];
    const float* W1r = (const float*)d_in[7];
    const float* a1  = (const float*)d_in[8];
    const float* b1  = (const float*)d_in[9];
    const float* W2l = (const float*)d_in[10];
    const float* W2r = (const float*)d_in[11];
    const float* a2  = (const float*)d_in[12];
    const float* b2  = (const float*)d_in[13];
    const float* W3l = (const float*)d_in[14];
    const float* W3r = (const float*)d_in[15];
    const float* a3  = (const float*)d_in[16];
    const float* b3  = (const float*)d_in[17];
    const float* g0  = (const float*)d_in[18];
    const float* be0 = (const float*)d_in[19];
    const float* m0  = (const float*)d_in[20];
    const float* v0  = (const float*)d_in[21];
    const float* g1  = (const float*)d_in[22];
    const float* be1 = (const float*)d_in[23];
    const float* m1  = (const float*)d_in[24];
    const float* v1  = (const float*)d_in[25];
    const float* g2  = (const float*)d_in[26];
    const float* be2 = (const float*)d_in[27];
    const float* m2  = (const float*)d_in[28];
    const float* v2  = (const float*)d_in[29];

    // ---- edge preprocessing (counting sort by dst; shared by all 4 layers) ----
    zero_hist_kernel<<<(NNODES + 255) / 256, 256>>>();
    hist_kernel<<<(ETOT + 255) / 256, 256>>>(ei);
    scan_kernel<<<1, 1024>>>();
    scatter_kernel<<<(ETOT + 255) / 256, 256>>>(ei);

    dim3 gemmGrid((NNODES + 127) / 128, 1);
    int edgeBlocks = NNODES / 8;   // 1 warp per node, 8 warps per block

    // ---- layer 0: input = x, output -> g_h1 (id 2) ----
    sgemm_kernel<128, 128, 16, 8, 8><<<gemmGrid, 256>>>(x, -1, 0, W0l, NNODES, 128, 128);
    sgemm_kernel<128, 128, 16, 8, 8><<<gemmGrid, 256>>>(x, -1, 1, W0r, NNODES, 128, 128);
    edge_full_kernel<<<edgeBlocks, 256>>>(a0, b0, g0, be0, m0, v0, 2);

    // ---- layer 1: g_h1 -> g_h2 (id 3) ----
    sgemm_kernel<128, 128, 16, 8, 8><<<gemmGrid, 256>>>(nullptr, 2, 0, W1l, NNODES, 128, 128);
    sgemm_kernel<128, 128, 16, 8, 8><<<gemmGrid, 256>>>(nullptr, 2, 1, W1r, NNODES, 128, 128);
    edge_full_kernel<<<edgeBlocks, 256>>>(a1, b1, g1, be1, m1, v1, 3);

    // ---- layer 2: g_h2 -> g_h1 (id 2) ----
    sgemm_kernel<128, 128, 16, 8, 8><<<gemmGrid, 256>>>(nullptr, 3, 0, W2l, NNODES, 128, 128);
    sgemm_kernel<128, 128, 16, 8, 8><<<gemmGrid, 256>>>(nullptr, 3, 1, W2r, NNODES, 128, 128);
    edge_full_kernel<<<edgeBlocks, 256>>>(a2, b2, g2, be2, m2, v2, 2);

    // ---- layer 3: g_h1 -> d_out ----
    sgemm_kernel<128, 16, 16, 8, 1><<<gemmGrid, 256>>>(nullptr, 2, 0, W3l, NNODES, OUTC, 128);
    sgemm_kernel<128, 16, 16, 8, 1><<<gemmGrid, 256>>>(nullptr, 2, 1, W3r, NNODES, OUTC, 128);
    edge_out_kernel<<<edgeBlocks, 256>>>(a3, b3, (float*)d_out);
}

// round 4
// speedup vs baseline: 1.3443x; 1.3443x over previous
#include <cuda_runtime.h>
#include <cuda_bf16.h>
#include <cstdint>

#define NNODES 50000
#define NEDGES 500000
#define ETOT   550000     // edges + self loops
#define HCDIM  128        // heads*hid for layers 0-2
#define OUTC   16
#define NSCANB ((NNODES + 1023) / 1024)   // 49

// -------- scratch (no cudaMalloc allowed) --------
__device__ __align__(16) float g_h1[(size_t)NNODES * HCDIM];
__device__ __align__(16) float g_h2[(size_t)NNODES * HCDIM];
__device__ __align__(16) float g_xl[(size_t)NNODES * HCDIM];
__device__ __align__(16) float g_xr[(size_t)NNODES * HCDIM];
__device__ int   g_srcbuf[ETOT];
__device__ int   g_seg[NNODES + 1];
__device__ int   g_hist[NNODES];
__device__ int   g_cursor[NNODES];
__device__ int   g_bsum[64];

__device__ __forceinline__ float* bufptr(int id) {
    switch (id) {
        case 0: return g_xl;
        case 1: return g_xr;
        case 2: return g_h1;
        default: return g_h2;
    }
}

__device__ __forceinline__ float lrelu(float v) { return v > 0.f ? v : 0.2f * v; }
__device__ __forceinline__ float elu1(float v)  { return v > 0.f ? v : expm1f(v); }

// packed f32x2 helpers (Blackwell FFMA2 — only reachable via PTX)
__device__ __forceinline__ void fma2(unsigned long long& d, unsigned long long a,
                                     unsigned long long b) {
    asm("fma.rn.f32x2 %0, %1, %2, %0;" : "+l"(d) : "l"(a), "l"(b));
}
__device__ __forceinline__ unsigned long long pack2(float x, float y) {
    unsigned long long r;
    asm("mov.b64 %0, {%1, %2};" : "=l"(r) : "f"(x), "f"(y));
    return r;
}
__device__ __forceinline__ float2 unpack2(unsigned long long v) {
    float2 r;
    asm("mov.b64 {%0, %1}, %2;" : "=f"(r.x), "=f"(r.y) : "l"(v));
    return r;
}

// -------- edge preprocessing: counting sort by dst --------
__global__ void zero_hist_kernel() {
    int i = blockIdx.x * blockDim.x + threadIdx.x;
    if (i < NNODES) g_hist[i] = 0;
}

// edge_index is int32 (JAX x64 disabled downgrades int64 -> int32)
__global__ void hist_kernel(const int* __restrict__ ei) {
    int i = blockIdx.x * blockDim.x + threadIdx.x;
    if (i >= ETOT) return;
    int d = (i < NEDGES) ? ei[NEDGES + i] : (i - NEDGES);
    atomicAdd(&g_hist[d], 1);
}

// grid-wide 3-phase exclusive scan of g_hist -> g_seg (+ g_cursor)
__global__ void scan1_kernel() {   // NSCANB blocks x 1024
    __shared__ int ws[32];
    int t = threadIdx.x, lane = t & 31, wid = t >> 5;
    int i = blockIdx.x * 1024 + t;
    int v = (i < NNODES) ? g_hist[i] : 0;
    int x = v;
#pragma unroll
    for (int d = 1; d < 32; d <<= 1) {
        int y = __shfl_up_sync(0xffffffffu, x, d);
        if (lane >= d) x += y;
    }
    if (lane == 31) ws[wid] = x;
    __syncthreads();
    if (wid == 0) {
        int w = ws[lane];
#pragma unroll
        for (int d = 1; d < 32; d <<= 1) {
            int y = __shfl_up_sync(0xffffffffu, w, d);
            if (lane >= d) w += y;
        }
        ws[lane] = w;
    }
    __syncthreads();
    int incl = x + (wid ? ws[wid - 1] : 0);
    if (i < NNODES) g_seg[i] = incl - v;          // block-local exclusive
    if (t == 1023) g_bsum[blockIdx.x] = incl;     // block total
}

__global__ void scan2_kernel() {   // 1 block x 64
    __shared__ int ws[2];
    int t = threadIdx.x, lane = t & 31, wid = t >> 5;
    int v = (t < NSCANB) ? g_bsum[t] : 0;
    int x = v;
#pragma unroll
    for (int d = 1; d < 32; d <<= 1) {
        int y = __shfl_up_sync(0xffffffffu, x, d);
        if (lane >= d) x += y;
    }
    if (lane == 31) ws[wid] = x;
    __syncthreads();
    int incl = x + (wid ? ws[0] : 0);
    if (t < NSCANB) g_bsum[t] = incl - v;         // exclusive block offsets
}

__global__ void scan3_kernel() {
    int i = blockIdx.x * blockDim.x + threadIdx.x;
    if (i < NNODES) {
        int s = g_seg[i] + g_bsum[i >> 10];
        g_seg[i] = s;
        g_cursor[i] = s;
    }
    if (i == 0) g_seg[NNODES] = ETOT;
}

__global__ void scatter_kernel(const int* __restrict__ ei) {
    int i = blockIdx.x * blockDim.x + threadIdx.x;
    if (i >= ETOT) return;
    int s, d;
    if (i < NEDGES) { s = ei[i]; d = ei[NEDGES + i]; }
    else            { s = d = i - NEDGES; }
    int p = atomicAdd(&g_cursor[d], 1);
    g_srcbuf[p] = s;
}

// -------- packed-f32x2 SGEMM: C[M,128] = A[M,128] @ B[128,128] --------
// BM=128, BN=128, BK=16, 256 threads. Thread (tx,ty), tx in 0..15, ty in 0..15.
// Each thread: 8 rows (ty+16i), 4 column PAIRS (cols tx*2+32*jp, +1) -> 8x8 outputs
// accumulated as f32x2 packed pairs via FFMA2.
__global__ __launch_bounds__(256, 2)
void sgemm2_kernel(const float* __restrict__ Aext, int aid, int cid,
                   const float* __restrict__ B, int M) {
    __shared__ __align__(16) float As[16][129];       // stride 129: conflict-free T-store
    __shared__ __align__(16) float Bs[16][136];       // stride 136: 8B-aligned pairs

    const float* A = (aid < 0) ? Aext : bufptr(aid);
    float* C = bufptr(cid);

    int t  = threadIdx.x;
    int tx = t & 15, ty = t >> 4;
    int mBase = blockIdx.x * 128;

    unsigned long long acc[8][4];
#pragma unroll
    for (int i = 0; i < 8; i++)
#pragma unroll
        for (int j = 0; j < 4; j++) acc[i][j] = 0ull;

    for (int kk = 0; kk < 128; kk += 16) {
        // A tile: 128x16, loaded as float4 along K, transposed into As[k][m]
#pragma unroll
        for (int r = 0; r < 2; r++) {
            int lin = t + r * 256;          // 0..511 float4 slots
            int m = lin >> 2, k4 = lin & 3;
            int gm = mBase + m;
            float4 av = (gm < M) ? *(const float4*)(A + (size_t)gm * 128 + kk + k4 * 4)
                                 : make_float4(0.f, 0.f, 0.f, 0.f);
            As[k4 * 4 + 0][m] = av.x;
            As[k4 * 4 + 1][m] = av.y;
            As[k4 * 4 + 2][m] = av.z;
            As[k4 * 4 + 3][m] = av.w;
        }
        // B tile: 16x128, float4 rows
#pragma unroll
        for (int r = 0; r < 2; r++) {
            int lin = t + r * 256;          // 0..511 float4 slots
            int k = lin >> 5, n4 = lin & 31;
            *(float4*)(&Bs[k][n4 * 4]) = *(const float4*)(B + (size_t)(kk + k) * 128 + n4 * 4);
        }
        __syncthreads();
#pragma unroll
        for (int k = 0; k < 16; k++) {
            unsigned long long bp[4];
#pragma unroll
            for (int jp = 0; jp < 4; jp++)
                bp[jp] = *(const unsigned long long*)(&Bs[k][tx * 2 + 32 * jp]);
            float a[8];
#pragma unroll
            for (int i = 0; i < 8; i++) a[i] = As[k][ty + 16 * i];
#pragma unroll
            for (int i = 0; i < 8; i++) {
                unsigned long long ad = pack2(a[i], a[i]);
#pragma unroll
                for (int jp = 0; jp < 4; jp++) fma2(acc[i][jp], ad, bp[jp]);
            }
        }
        __syncthreads();
    }
#pragma unroll
    for (int i = 0; i < 8; i++) {
        int gm = mBase + ty + 16 * i;
        if (gm >= M) continue;
#pragma unroll
        for (int jp = 0; jp < 4; jp++) {
            float2 r = unpack2(acc[i][jp]);
            *(float2*)(C + (size_t)gm * 128 + tx * 2 + 32 * jp) = r;
        }
    }
}

// -------- small fp32 SGEMM for layer 3 (Nn=16) --------
template <int BM, int BN, int BK, int TM, int TN>
__global__ void sgemm_kernel(const float* __restrict__ Aext, int aid, int cid,
                             const float* __restrict__ B, int M, int Nn, int K) {
    constexpr int TX = BN / TN;
    constexpr int TY = BM / TM;
    constexpr int NT = TX * TY;
    __shared__ float As[BK][BM];
    __shared__ float Bs[BK][BN + 4];

    const float* A = (aid < 0) ? Aext : bufptr(aid);
    float* C = bufptr(cid);

    int t = threadIdx.x;
    int tx = t % TX, ty = t / TX;
    int mBase = blockIdx.x * BM;
    int nBase = blockIdx.y * BN;

    float acc[TM][TN];
#pragma unroll
    for (int i = 0; i < TM; i++)
#pragma unroll
        for (int j = 0; j < TN; j++) acc[i][j] = 0.f;

    for (int kk = 0; kk < K; kk += BK) {
        for (int i = t; i < BM * BK; i += NT) {
            int m = i / BK, k = i % BK;
            int gm = mBase + m;
            As[k][m] = (gm < M) ? A[(size_t)gm * K + kk + k] : 0.f;
        }
        for (int i = t; i < BK * BN; i += NT) {
            int k = i / BN, n = i % BN;
            Bs[k][n] = B[(size_t)(kk + k) * Nn + nBase + n];
        }
        __syncthreads();
#pragma unroll
        for (int k = 0; k < BK; k++) {
            float a[TM], b[TN];
#pragma unroll
            for (int i = 0; i < TM; i++) a[i] = As[k][ty + TY * i];
#pragma unroll
            for (int j = 0; j < TN; j++) b[j] = Bs[k][tx + TX * j];
#pragma unroll
            for (int i = 0; i < TM; i++)
#pragma unroll
                for (int j = 0; j < TN; j++)
                    acc[i][j] = fmaf(a[i], b[j], acc[i][j]);
        }
        __syncthreads();
    }
#pragma unroll
    for (int i = 0; i < TM; i++) {
        int gm = mBase + ty + TY * i;
        if (gm >= M) continue;
#pragma unroll
        for (int j = 0; j < TN; j++) {
            int gn = nBase + tx + TX * j;
            C[(size_t)gm * Nn + gn] = acc[i][j];
        }
    }
}

// -------- edge pass, layers 0-2: softmax-aggregate + bias + BN + ELU fused --------
__global__ void edge_full_kernel(const float* __restrict__ att,
                                 const float* __restrict__ bias,
                                 const float* __restrict__ bg,
                                 const float* __restrict__ bb,
                                 const float* __restrict__ bm,
                                 const float* __restrict__ bv,
                                 int outid) {
    int gw = (blockIdx.x * blockDim.x + threadIdx.x) >> 5;
    if (gw >= NNODES) return;
    int lane = threadIdx.x & 31;
    int n = gw;
    int c0 = lane * 4;

    const float4 xrv = *(const float4*)(g_xr + (size_t)n * HCDIM + c0);
    const float4 av  = *(const float4*)(att + c0);

    int beg = g_seg[n], end = g_seg[n + 1];
    float acc0 = 0.f, acc1 = 0.f, acc2 = 0.f, acc3 = 0.f, den = 0.f;

    for (int e = beg; e < end; e += 2) {
        int s0 = g_srcbuf[e];
        bool two = (e + 1 < end);
        int s1 = two ? g_srcbuf[e + 1] : s0;
        float4 x0 = *(const float4*)(g_xl + (size_t)s0 * HCDIM + c0);
        float4 x1 = *(const float4*)(g_xl + (size_t)s1 * HCDIM + c0);
        {
            float p = lrelu(x0.x + xrv.x) * av.x + lrelu(x0.y + xrv.y) * av.y
                    + lrelu(x0.z + xrv.z) * av.z + lrelu(x0.w + xrv.w) * av.w;
            p += __shfl_xor_sync(0xffffffffu, p, 1);
            p += __shfl_xor_sync(0xffffffffu, p, 2);
            float aE = __expf(p);   // max-subtraction skipped: |logit| ~ O(1)
            den += aE;
            acc0 = fmaf(x0.x, aE, acc0); acc1 = fmaf(x0.y, aE, acc1);
            acc2 = fmaf(x0.z, aE, acc2); acc3 = fmaf(x0.w, aE, acc3);
        }
        {
            float p = lrelu(x1.x + xrv.x) * av.x + lrelu(x1.y + xrv.y) * av.y
                    + lrelu(x1.z + xrv.z) * av.z + lrelu(x1.w + xrv.w) * av.w;
            p += __shfl_xor_sync(0xffffffffu, p, 1);
            p += __shfl_xor_sync(0xffffffffu, p, 2);
            float aE = two ? __expf(p) : 0.f;
            den += aE;
            acc0 = fmaf(x1.x, aE, acc0); acc1 = fmaf(x1.y, aE, acc1);
            acc2 = fmaf(x1.z, aE, acc2); acc3 = fmaf(x1.w, aE, acc3);
        }
    }

    float inv = 1.f / den;   // self-loop guarantees den > 0
    float4 bi  = *(const float4*)(bias + c0);
    float4 gg  = *(const float4*)(bg + c0);
    float4 bev = *(const float4*)(bb + c0);
    float4 mm  = *(const float4*)(bm + c0);
    float4 vv  = *(const float4*)(bv + c0);

    float4 r;
    r.x = elu1((acc0 * inv + bi.x - mm.x) * rsqrtf(vv.x + 1e-5f) * gg.x + bev.x);
    r.y = elu1((acc1 * inv + bi.y - mm.y) * rsqrtf(vv.y + 1e-5f) * gg.y + bev.y);
    r.z = elu1((acc2 * inv + bi.z - mm.z) * rsqrtf(vv.z + 1e-5f) * gg.z + bev.z);
    r.w = elu1((acc3 * inv + bi.w - mm.w) * rsqrtf(vv.w + 1e-5f) * gg.w + bev.w);

    float* out = bufptr(outid);
    *(float4*)(out + (size_t)n * HCDIM + c0) = r;
}

// -------- edge pass, layer 3 (1 head, 16 channels) -> d_out --------
__global__ void edge_out_kernel(const float* __restrict__ att,
                                const float* __restrict__ bias,
                                float* __restrict__ out) {
    int gw = (blockIdx.x * blockDim.x + threadIdx.x) >> 5;
    if (gw >= NNODES) return;
    int lane = threadIdx.x & 31;
    int c = lane & 15;
    int half = lane >> 4;
    int n = gw;

    float xrv = g_xr[(size_t)n * OUTC + c];
    float av  = att[c];
    int beg = g_seg[n], end = g_seg[n + 1];
    float acc = 0.f, den = 0.f;
    int iters = (end - beg + 1) >> 1;
    for (int i = 0; i < iters; i++) {
        int e = beg + 2 * i + half;
        bool valid = (e < end);
        int s = valid ? g_srcbuf[e] : g_srcbuf[beg];
        float xlv = g_xl[(size_t)s * OUTC + c];
        float p = lrelu(xlv + xrv) * av;
        p += __shfl_xor_sync(0xffffffffu, p, 1);
        p += __shfl_xor_sync(0xffffffffu, p, 2);
        p += __shfl_xor_sync(0xffffffffu, p, 4);
        p += __shfl_xor_sync(0xffffffffu, p, 8);
        float aE = valid ? __expf(p) : 0.f;
        den += aE;
        acc = fmaf(xlv, aE, acc);
    }
    acc += __shfl_xor_sync(0xffffffffu, acc, 16);
    den += __shfl_xor_sync(0xffffffffu, den, 16);
    if (half == 0) out[(size_t)n * OUTC + c] = acc / den + bias[c];
}

// -------- orchestration --------
extern "C" void kernel_launch(void* const* d_in, const int* in_sizes, int n_in,
                              void* d_out, int out_size) {
    const float* x  = (const float*)d_in[0];
    const int*   ei = (const int*)d_in[1];   // int32
    const float* W0l = (const float*)d_in[2];
    const float* W0r = (const float*)d_in[3];
    const float* a0  = (const float*)d_in[4];
    const float* b0  = (const float*)d_in[5];
    const float* W1l = (const float*)d_in[6];
    const float* W1r = (const float*)d_in[7];
    const float* a1  = (const float*)d_in[8];
    const float* b1  = (const float*)d_in[9];
    const float* W2l = (const float*)d_in[10];
    const float* W2r = (const float*)d_in[11];
    const float* a2  = (const float*)d_in[12];
    const float* b2  = (const float*)d_in[13];
    const float* W3l = (const float*)d_in[14];
    const float* W3r = (const float*)d_in[15];
    const float* a3  = (const float*)d_in[16];
    const float* b3  = (const float*)d_in[17];
    const float* g0  = (const float*)d_in[18];
    const float* be0 = (const float*)d_in[19];
    const float* m0  = (const float*)d_in[20];
    const float* v0  = (const float*)d_in[21];
    const float* g1  = (const float*)d_in[22];
    const float* be1 = (const float*)d_in[23];
    const float* m1  = (const float*)d_in[24];
    const float* v1  = (const float*)d_in[25];
    const float* g2  = (const float*)d_in[26];
    const float* be2 = (const float*)d_in[27];
    const float* m2  = (const float*)d_in[28];
    const float* v2  = (const float*)d_in[29];

    // ---- edge preprocessing (counting sort by dst; shared by all 4 layers) ----
    zero_hist_kernel<<<(NNODES + 255) / 256, 256>>>();
    hist_kernel<<<(ETOT + 255) / 256, 256>>>(ei);
    scan1_kernel<<<NSCANB, 1024>>>();
    scan2_kernel<<<1, 64>>>();
    scan3_kernel<<<(NNODES + 255) / 256, 256>>>();
    scatter_kernel<<<(ETOT + 255) / 256, 256>>>(ei);

    int gemmBlocks = (NNODES + 127) / 128;
    int edgeBlocks = NNODES / 8;   // 1 warp per node, 8 warps per block

    // ---- layer 0: input = x -> g_h1 (id 2) ----
    sgemm2_kernel<<<gemmBlocks, 256>>>(x, -1, 0, W0l, NNODES);
    sgemm2_kernel<<<gemmBlocks, 256>>>(x, -1, 1, W0r, NNODES);
    edge_full_kernel<<<edgeBlocks, 256>>>(a0, b0, g0, be0, m0, v0, 2);

    // ---- layer 1: g_h1 -> g_h2 (id 3) ----
    sgemm2_kernel<<<gemmBlocks, 256>>>(nullptr, 2, 0, W1l, NNODES);
    sgemm2_kernel<<<gemmBlocks, 256>>>(nullptr, 2, 1, W1r, NNODES);
    edge_full_kernel<<<edgeBlocks, 256>>>(a1, b1, g1, be1, m1, v1, 3);

    // ---- layer 2: g_h2 -> g_h1 (id 2) ----
    sgemm2_kernel<<<gemmBlocks, 256>>>(nullptr, 3, 0, W2l, NNODES);
    sgemm2_kernel<<<gemmBlocks, 256>>>(nullptr, 3, 1, W2r, NNODES);
    edge_full_kernel<<<edgeBlocks, 256>>>(a2, b2, g2, be2, m2, v2, 2);

    // ---- layer 3: g_h1 -> d_out ----
    sgemm_kernel<128, 16, 16, 8, 1><<<gemmBlocks, 256>>>(nullptr, 2, 0, W3l, NNODES, OUTC, 128);
    sgemm_kernel<128, 16, 16, 8, 1><<<gemmBlocks, 256>>>(nullptr, 2, 1, W3r, NNODES, OUTC, 128);
    edge_out_kernel<<<edgeBlocks, 256>>>(a3, b3, (float*)d_out);
}

// round 5
// speedup vs baseline: 1.7307x; 1.2874x over previous
#include <cuda_runtime.h>
#include <cuda_bf16.h>
#include <cstdint>

#define NNODES 50000
#define NEDGES 500000
#define ETOT   550000     // edges + self loops
#define HCDIM  128
#define OUTC   16
#define NSCANB ((NNODES + 1023) / 1024)   // 49
#define KW     64         // uint32 (bf16x2) per 128-feature row

// -------- scratch (no cudaMalloc allowed) --------
__device__ __align__(16) float g_xl[(size_t)NNODES * HCDIM];
__device__ __align__(16) float g_xr[(size_t)NNODES * HCDIM];
__device__ __align__(16) unsigned g_Ahi[2][(size_t)NNODES * KW];   // split-bf16 A, permuted
__device__ __align__(16) unsigned g_Alo[2][(size_t)NNODES * KW];
__device__ __align__(16) unsigned g_Whi[6][128 * KW];              // W^T split-bf16, permuted
__device__ __align__(16) unsigned g_Wlo[6][128 * KW];
__device__ int g_srcbuf[ETOT];
__device__ int g_seg[NNODES + 1];
__device__ int g_hist[NNODES];
__device__ int g_cursor[NNODES];
__device__ int g_bsum[64];

__device__ __forceinline__ float lrelu(float v) { return v > 0.f ? v : 0.2f * v; }
__device__ __forceinline__ float elu1(float v)  { return v > 0.f ? v : expm1f(v); }

// ---- bf16 split helpers ----
__device__ __forceinline__ unsigned bf16x2(float x, float y) {   // lo=x, hi=y
    unsigned r;
    asm("cvt.rn.bf16x2.f32 %0, %1, %2;" : "=r"(r) : "f"(y), "f"(x));
    return r;
}
__device__ __forceinline__ float bflo(unsigned u) { return __uint_as_float(u << 16); }
__device__ __forceinline__ float bfhi(unsigned u) { return __uint_as_float(u & 0xffff0000u); }

// pair index p (=k/2, 0..63) -> physical uint32 slot (pairs (k,k+8) adjacent per k16 block)
__device__ __forceinline__ int phys_pair(int p) {
    return ((p >> 3) << 3) + ((p & 3) << 1) + ((p >> 2) & 1);
}

// write 4 consecutive channels (c0 = q*4) of one row as split bf16 in permuted layout
__device__ __forceinline__ void store_split(unsigned* hiRow, unsigned* loRow,
                                            int q, float4 v) {
    int p0 = q * 2;
    int i0 = phys_pair(p0), i1 = phys_pair(p0 + 1);
    unsigned h0 = bf16x2(v.x, v.y);
    unsigned l0 = bf16x2(v.x - bflo(h0), v.y - bfhi(h0));
    unsigned h1 = bf16x2(v.z, v.w);
    unsigned l1 = bf16x2(v.z - bflo(h1), v.w - bfhi(h1));
    hiRow[i0] = h0; hiRow[i1] = h1;
    loRow[i0] = l0; loRow[i1] = l1;
}

// -------- edge preprocessing: counting sort by dst --------
__global__ void zero_hist_kernel() {
    int i = blockIdx.x * blockDim.x + threadIdx.x;
    if (i < NNODES) g_hist[i] = 0;
}

__global__ void hist_kernel(const int* __restrict__ ei) {
    int i = blockIdx.x * blockDim.x + threadIdx.x;
    if (i >= ETOT) return;
    int d = (i < NEDGES) ? ei[NEDGES + i] : (i - NEDGES);
    atomicAdd(&g_hist[d], 1);
}

__global__ void scan1_kernel() {   // NSCANB blocks x 1024
    __shared__ int ws[32];
    int t = threadIdx.x, lane = t & 31, wid = t >> 5;
    int i = blockIdx.x * 1024 + t;
    int v = (i < NNODES) ? g_hist[i] : 0;
    int x = v;
#pragma unroll
    for (int d = 1; d < 32; d <<= 1) {
        int y = __shfl_up_sync(0xffffffffu, x, d);
        if (lane >= d) x += y;
    }
    if (lane == 31) ws[wid] = x;
    __syncthreads();
    if (wid == 0) {
        int w = ws[lane];
#pragma unroll
        for (int d = 1; d < 32; d <<= 1) {
            int y = __shfl_up_sync(0xffffffffu, w, d);
            if (lane >= d) w += y;
        }
        ws[lane] = w;
    }
    __syncthreads();
    int incl = x + (wid ? ws[wid - 1] : 0);
    if (i < NNODES) g_seg[i] = incl - v;
    if (t == 1023) g_bsum[blockIdx.x] = incl;
}

__global__ void scan2_kernel() {   // 1 block x 64
    __shared__ int ws[2];
    int t = threadIdx.x, lane = t & 31, wid = t >> 5;
    int v = (t < NSCANB) ? g_bsum[t] : 0;
    int x = v;
#pragma unroll
    for (int d = 1; d < 32; d <<= 1) {
        int y = __shfl_up_sync(0xffffffffu, x, d);
        if (lane >= d) x += y;
    }
    if (lane == 31) ws[wid] = x;
    __syncthreads();
    int incl = x + (wid ? ws[0] : 0);
    if (t < NSCANB) g_bsum[t] = incl - v;
}

__global__ void scan3_kernel() {
    int i = blockIdx.x * blockDim.x + threadIdx.x;
    if (i < NNODES) {
        int s = g_seg[i] + g_bsum[i >> 10];
        g_seg[i] = s;
        g_cursor[i] = s;
    }
    if (i == 0) g_seg[NNODES] = ETOT;
}

__global__ void scatter_kernel(const int* __restrict__ ei) {
    int i = blockIdx.x * blockDim.x + threadIdx.x;
    if (i >= ETOT) return;
    int s, d;
    if (i < NEDGES) { s = ei[i]; d = ei[NEDGES + i]; }
    else            { s = d = i - NEDGES; }
    int p = atomicAdd(&g_cursor[d], 1);
    g_srcbuf[p] = s;
}

// -------- conversions to split-bf16 permuted layout --------
__global__ void convert_x_kernel(const float* __restrict__ x) {
    int tid = blockIdx.x * blockDim.x + threadIdx.x;
    if (tid >= NNODES * 32) return;
    int m = tid >> 5, q = tid & 31;
    float4 v = *(const float4*)(x + (size_t)m * 128 + q * 4);
    store_split(&g_Ahi[0][(size_t)m * KW], &g_Alo[0][(size_t)m * KW], q, v);
}

// W fp32 [128][128] row-major -> W^T split-bf16 permuted [n][phys]
__global__ void convert_w_kernel(const float* W0, const float* W1, const float* W2,
                                 const float* W3, const float* W4, const float* W5) {
    int widx = blockIdx.y;
    const float* W;
    switch (widx) {
        case 0: W = W0; break;  case 1: W = W1; break;
        case 2: W = W2; break;  case 3: W = W3; break;
        case 4: W = W4; break;  default: W = W5; break;
    }
    int idx = blockIdx.x * blockDim.x + threadIdx.x;   // 0..8191
    if (idx >= 128 * 64) return;
    int n = idx >> 6, p = idx & 63;
    float a = W[(size_t)(2 * p) * 128 + n];
    float b = W[(size_t)(2 * p + 1) * 128 + n];
    unsigned h = bf16x2(a, b);
    unsigned l = bf16x2(a - bflo(h), b - bfhi(h));
    int dst = n * KW + phys_pair(p);
    g_Whi[widx][dst] = h;
    g_Wlo[widx][dst] = l;
}

// -------- split-bf16 MMA GEMM: [M,128] x (Wl[128,128] | Wr[128,128]) -> g_xl, g_xr --------
// block tile m64 x n256, 8 warps (m32 x n64 each), BK=32 (2 k16 steps / chunk, 4 chunks)
#define SASTRIDE 24   // uint32 per smem row (48 bf16): bank shift 24 -> conflict-free
__global__ __launch_bounds__(256, 2)
void mma_gemm_kernel(int aset, int wl, int wr) {
    __shared__ unsigned sA[2][64][SASTRIDE];
    __shared__ unsigned sB[2][256][SASTRIDE];

    const unsigned* aHi = g_Ahi[aset];
    const unsigned* aLo = g_Alo[aset];

    int t = threadIdx.x;
    int warp = t >> 5, lane = t & 31;
    int mt = warp & 1, nq = warp >> 1;       // warp tile: rows mt*32.., cols nq*64..
    int mBase = blockIdx.x * 64;
    int r = lane >> 2, c = lane & 3;

    float acc[2][8][4];
#pragma unroll
    for (int i = 0; i < 2; i++)
#pragma unroll
        for (int j = 0; j < 8; j++)
#pragma unroll
            for (int k = 0; k < 4; k++) acc[i][j][k] = 0.f;

    for (int chunk = 0; chunk < 4; chunk++) {
        // fill sA: 2 splits x 64 rows x 16 uint32
#pragma unroll
        for (int rep = 0; rep < 2; rep++) {
            int lin = t + rep * 256;          // 0..511
            int split = lin >> 8;
            int q = lin & 255;
            int m = q >> 2, c4 = q & 3;
            int gm = mBase + m;
            uint4 v = make_uint4(0u, 0u, 0u, 0u);
            if (gm < NNODES) {
                const unsigned* src = (split ? aLo : aHi) + (size_t)gm * KW + chunk * 16 + c4 * 4;
                v = *(const uint4*)src;
            }
            *(uint4*)&sA[split][m][c4 * 4] = v;
        }
        // fill sB: 2 splits x 256 rows x 16 uint32
#pragma unroll
        for (int rep = 0; rep < 8; rep++) {
            int lin = t + rep * 256;          // 0..2047
            int split = lin >> 10;
            int q = lin & 1023;
            int n = q >> 2, c4 = q & 3;
            const unsigned* src;
            if (n < 128) src = (split ? g_Wlo[wl] : g_Whi[wl]) + n * KW;
            else         src = (split ? g_Wlo[wr] : g_Whi[wr]) + (n - 128) * KW;
            *(uint4*)&sB[split][n][c4 * 4] = *(const uint4*)(src + chunk * 16 + c4 * 4);
        }
        __syncthreads();

#pragma unroll
        for (int ks = 0; ks < 2; ks++) {
            unsigned Ah[2][4], Al[2][4];
#pragma unroll
            for (int tile = 0; tile < 2; tile++) {
                int row0 = mt * 32 + tile * 16 + r;
                uint2 u0 = *(const uint2*)&sA[0][row0][ks * 8 + 2 * c];
                uint2 u1 = *(const uint2*)&sA[0][row0 + 8][ks * 8 + 2 * c];
                Ah[tile][0] = u0.x; Ah[tile][2] = u0.y;
                Ah[tile][1] = u1.x; Ah[tile][3] = u1.y;
                uint2 v0 = *(const uint2*)&sA[1][row0][ks * 8 + 2 * c];
                uint2 v1 = *(const uint2*)&sA[1][row0 + 8][ks * 8 + 2 * c];
                Al[tile][0] = v0.x; Al[tile][2] = v0.y;
                Al[tile][1] = v1.x; Al[tile][3] = v1.y;
            }
#pragma unroll
            for (int nt = 0; nt < 8; nt++) {
                int n = nq * 64 + nt * 8 + r;
                uint2 bh = *(const uint2*)&sB[0][n][ks * 8 + 2 * c];
                uint2 bl = *(const uint2*)&sB[1][n][ks * 8 + 2 * c];
#pragma unroll
                for (int tile = 0; tile < 2; tile++) {
                    float* cc = acc[tile][nt];
                    asm volatile(
                        "mma.sync.aligned.m16n8k16.row.col.f32.bf16.bf16.f32 "
                        "{%0,%1,%2,%3}, {%4,%5,%6,%7}, {%8,%9}, {%0,%1,%2,%3};\n"
                        : "+f"(cc[0]), "+f"(cc[1]), "+f"(cc[2]), "+f"(cc[3])
                        : "r"(Ah[tile][0]), "r"(Ah[tile][1]), "r"(Ah[tile][2]), "r"(Ah[tile][3]),
                          "r"(bh.x), "r"(bh.y));
                    asm volatile(
                        "mma.sync.aligned.m16n8k16.row.col.f32.bf16.bf16.f32 "
                        "{%0,%1,%2,%3}, {%4,%5,%6,%7}, {%8,%9}, {%0,%1,%2,%3};\n"
                        : "+f"(cc[0]), "+f"(cc[1]), "+f"(cc[2]), "+f"(cc[3])
                        : "r"(Ah[tile][0]), "r"(Ah[tile][1]), "r"(Ah[tile][2]), "r"(Ah[tile][3]),
                          "r"(bl.x), "r"(bl.y));
                    asm volatile(
                        "mma.sync.aligned.m16n8k16.row.col.f32.bf16.bf16.f32 "
                        "{%0,%1,%2,%3}, {%4,%5,%6,%7}, {%8,%9}, {%0,%1,%2,%3};\n"
                        : "+f"(cc[0]), "+f"(cc[1]), "+f"(cc[2]), "+f"(cc[3])
                        : "r"(Al[tile][0]), "r"(Al[tile][1]), "r"(Al[tile][2]), "r"(Al[tile][3]),
                          "r"(bh.x), "r"(bh.y));
                }
            }
        }
        __syncthreads();
    }

    // epilogue: scatter fp32 to g_xl / g_xr
    int c2 = c * 2;
#pragma unroll
    for (int tile = 0; tile < 2; tile++) {
        int gm0 = mBase + mt * 32 + tile * 16 + r;
#pragma unroll
        for (int nt = 0; nt < 8; nt++) {
            int n = nq * 64 + nt * 8 + c2;
            float* dst = (n < 128) ? (g_xl + n) : (g_xr + n - 128);
            if (gm0 < NNODES)
                *(float2*)(dst + (size_t)gm0 * 128) = make_float2(acc[tile][nt][0], acc[tile][nt][1]);
            if (gm0 + 8 < NNODES)
                *(float2*)(dst + (size_t)(gm0 + 8) * 128) = make_float2(acc[tile][nt][2], acc[tile][nt][3]);
        }
    }
}

// -------- small fp32 GEMM for layer 3: A(split bf16) [M,128] @ W [128,16] --------
__global__ void sgemm16_kernel(int aset, int cid, const float* __restrict__ B) {
    __shared__ float As[16][129];
    __shared__ float Bs[16][20];
    const unsigned* aHi = g_Ahi[aset];
    const unsigned* aLo = g_Alo[aset];
    float* C = cid ? g_xr : g_xl;

    int t = threadIdx.x;
    int tx = t & 15, ty = t >> 4;
    int mBase = blockIdx.x * 128;

    float acc[8];
#pragma unroll
    for (int i = 0; i < 8; i++) acc[i] = 0.f;

    for (int kk = 0; kk < 128; kk += 16) {
        for (int i = t; i < 128 * 16; i += 256) {
            int m = i >> 4, k = i & 15;
            int gm = mBase + m;
            float val = 0.f;
            if (gm < NNODES) {
                int klog = kk + k;
                int p = klog >> 1, odd = klog & 1;
                int idx = phys_pair(p);
                unsigned h = aHi[(size_t)gm * KW + idx];
                unsigned l = aLo[(size_t)gm * KW + idx];
                float fh = odd ? bfhi(h) : bflo(h);
                float fl = odd ? bfhi(l) : bflo(l);
                val = fh + fl;
            }
            As[k][m] = val;
        }
        if (t < 16 * 16) {
            int k = t >> 4, n = t & 15;
            Bs[k][n] = B[(size_t)(kk + k) * 16 + n];
        }
        __syncthreads();
#pragma unroll
        for (int k = 0; k < 16; k++) {
            float b = Bs[k][tx];
#pragma unroll
            for (int i = 0; i < 8; i++)
                acc[i] = fmaf(As[k][ty + 16 * i], b, acc[i]);
        }
        __syncthreads();
    }
#pragma unroll
    for (int i = 0; i < 8; i++) {
        int gm = mBase + ty + 16 * i;
        if (gm < NNODES) C[(size_t)gm * OUTC + tx] = acc[i];
    }
}

// -------- edge pass, layers 0-2 (fused softmax/agg/bias/BN/ELU, emits split bf16) --------
__global__ void edge_full_kernel(const float* __restrict__ att,
                                 const float* __restrict__ bias,
                                 const float* __restrict__ bg,
                                 const float* __restrict__ bb,
                                 const float* __restrict__ bm,
                                 const float* __restrict__ bv,
                                 int oset) {
    int gw = (blockIdx.x * blockDim.x + threadIdx.x) >> 5;
    if (gw >= NNODES) return;
    int lane = threadIdx.x & 31;
    int n = gw;
    int c0 = lane * 4;

    const float4 xrv = *(const float4*)(g_xr + (size_t)n * HCDIM + c0);
    const float4 av  = *(const float4*)(att + c0);

    int beg = g_seg[n], end = g_seg[n + 1];
    float acc0 = 0.f, acc1 = 0.f, acc2 = 0.f, acc3 = 0.f, den = 0.f;

    for (int e = beg; e < end; e += 2) {
        int s0 = g_srcbuf[e];
        bool two = (e + 1 < end);
        int s1 = two ? g_srcbuf[e + 1] : s0;
        float4 x0 = *(const float4*)(g_xl + (size_t)s0 * HCDIM + c0);
        float4 x1 = *(const float4*)(g_xl + (size_t)s1 * HCDIM + c0);
        {
            float p = lrelu(x0.x + xrv.x) * av.x + lrelu(x0.y + xrv.y) * av.y
                    + lrelu(x0.z + xrv.z) * av.z + lrelu(x0.w + xrv.w) * av.w;
            p += __shfl_xor_sync(0xffffffffu, p, 1);
            p += __shfl_xor_sync(0xffffffffu, p, 2);
            float aE = __expf(p);
            den += aE;
            acc0 = fmaf(x0.x, aE, acc0); acc1 = fmaf(x0.y, aE, acc1);
            acc2 = fmaf(x0.z, aE, acc2); acc3 = fmaf(x0.w, aE, acc3);
        }
        {
            float p = lrelu(x1.x + xrv.x) * av.x + lrelu(x1.y + xrv.y) * av.y
                    + lrelu(x1.z + xrv.z) * av.z + lrelu(x1.w + xrv.w) * av.w;
            p += __shfl_xor_sync(0xffffffffu, p, 1);
            p += __shfl_xor_sync(0xffffffffu, p, 2);
            float aE = two ? __expf(p) : 0.f;
            den += aE;
            acc0 = fmaf(x1.x, aE, acc0); acc1 = fmaf(x1.y, aE, acc1);
            acc2 = fmaf(x1.z, aE, acc2); acc3 = fmaf(x1.w, aE, acc3);
        }
    }

    float inv = 1.f / den;
    float4 bi  = *(const float4*)(bias + c0);
    float4 gg  = *(const float4*)(bg + c0);
    float4 bev = *(const float4*)(bb + c0);
    float4 mm  = *(const float4*)(bm + c0);
    float4 vv  = *(const float4*)(bv + c0);

    float4 r;
    r.x = elu1((acc0 * inv + bi.x - mm.x) * rsqrtf(vv.x + 1e-5f) * gg.x + bev.x);
    r.y = elu1((acc1 * inv + bi.y - mm.y) * rsqrtf(vv.y + 1e-5f) * gg.y + bev.y);
    r.z = elu1((acc2 * inv + bi.z - mm.z) * rsqrtf(vv.z + 1e-5f) * gg.z + bev.z);
    r.w = elu1((acc3 * inv + bi.w - mm.w) * rsqrtf(vv.w + 1e-5f) * gg.w + bev.w);

    store_split(&g_Ahi[oset][(size_t)n * KW], &g_Alo[oset][(size_t)n * KW], lane, r);
}

// -------- edge pass, layer 3 -> d_out --------
__global__ void edge_out_kernel(const float* __restrict__ att,
                                const float* __restrict__ bias,
                                float* __restrict__ out) {
    int gw = (blockIdx.x * blockDim.x + threadIdx.x) >> 5;
    if (gw >= NNODES) return;
    int lane = threadIdx.x & 31;
    int c = lane & 15;
    int half = lane >> 4;
    int n = gw;

    float xrv = g_xr[(size_t)n * OUTC + c];
    float av  = att[c];
    int beg = g_seg[n], end = g_seg[n + 1];
    float acc = 0.f, den = 0.f;
    int iters = (end - beg + 1) >> 1;
    for (int i = 0; i < iters; i++) {
        int e = beg + 2 * i + half;
        bool valid = (e < end);
        int s = valid ? g_srcbuf[e] : g_srcbuf[beg];
        float xlv = g_xl[(size_t)s * OUTC + c];
        float p = lrelu(xlv + xrv) * av;
        p += __shfl_xor_sync(0xffffffffu, p, 1);
        p += __shfl_xor_sync(0xffffffffu, p, 2);
        p += __shfl_xor_sync(0xffffffffu, p, 4);
        p += __shfl_xor_sync(0xffffffffu, p, 8);
        float aE = valid ? __expf(p) : 0.f;
        den += aE;
        acc = fmaf(xlv, aE, acc);
    }
    acc += __shfl_xor_sync(0xffffffffu, acc, 16);
    den += __shfl_xor_sync(0xffffffffu, den, 16);
    if (half == 0) out[(size_t)n * OUTC + c] = acc / den + bias[c];
}

// -------- orchestration --------
extern "C" void kernel_launch(void* const* d_in, const int* in_sizes, int n_in,
                              void* d_out, int out_size) {
    const float* x  = (const float*)d_in[0];
    const int*   ei = (const int*)d_in[1];
    const float* W0l = (const float*)d_in[2];
    const float* W0r = (const float*)d_in[3];
    const float* a0  = (const float*)d_in[4];
    const float* b0  = (const float*)d_in[5];
    const float* W1l = (const float*)d_in[6];
    const float* W1r = (const float*)d_in[7];
    const float* a1  = (const float*)d_in[8];
    const float* b1  = (const float*)d_in[9];
    const float* W2l = (const float*)d_in[10];
    const float* W2r = (const float*)d_in[11];
    const float* a2  = (const float*)d_in[12];
    const float* b2  = (const float*)d_in[13];
    const float* W3l = (const float*)d_in[14];
    const float* W3r = (const float*)d_in[15];
    const float* a3  = (const float*)d_in[16];
    const float* b3  = (const float*)d_in[17];
    const float* g0  = (const float*)d_in[18];
    const float* be0 = (const float*)d_in[19];
    const float* m0  = (const float*)d_in[20];
    const float* v0  = (const float*)d_in[21];
    const float* g1  = (const float*)d_in[22];
    const float* be1 = (const float*)d_in[23];
    const float* m1  = (const float*)d_in[24];
    const float* v1  = (const float*)d_in[25];
    const float* g2  = (const float*)d_in[26];
    const float* be2 = (const float*)d_in[27];
    const float* m2  = (const float*)d_in[28];
    const float* v2  = (const float*)d_in[29];

    // ---- edge preprocessing ----
    zero_hist_kernel<<<(NNODES + 255) / 256, 256>>>();
    hist_kernel<<<(ETOT + 255) / 256, 256>>>(ei);
    scan1_kernel<<<NSCANB, 1024>>>();
    scan2_kernel<<<1, 64>>>();
    scan3_kernel<<<(NNODES + 255) / 256, 256>>>();
    scatter_kernel<<<(ETOT + 255) / 256, 256>>>(ei);

    // ---- conversions ----
    convert_w_kernel<<<dim3(32, 6), 256>>>(W0l, W0r, W1l, W1r, W2l, W2r);
    convert_x_kernel<<<(NNODES * 32 + 255) / 256, 256>>>(x);

    int gemmBlocks = (NNODES + 63) / 64;   // 782
    int edgeBlocks = NNODES / 8;

    // ---- layer 0: A set0 -> xl/xr; edge -> A set1 ----
    mma_gemm_kernel<<<gemmBlocks, 256>>>(0, 0, 1);
    edge_full_kernel<<<edgeBlocks, 256>>>(a0, b0, g0, be0, m0, v0, 1);

    // ---- layer 1: A set1 -> xl/xr; edge -> A set0 ----
    mma_gemm_kernel<<<gemmBlocks, 256>>>(1, 2, 3);
    edge_full_kernel<<<edgeBlocks, 256>>>(a1, b1, g1, be1, m1, v1, 0);

    // ---- layer 2: A set0 -> xl/xr; edge -> A set1 ----
    mma_gemm_kernel<<<gemmBlocks, 256>>>(0, 4, 5);
    edge_full_kernel<<<edgeBlocks, 256>>>(a2, b2, g2, be2, m2, v2, 1);

    // ---- layer 3: A set1 (small GEMMs) -> xl/xr; edge -> d_out ----
    int smallBlocks = (NNODES + 127) / 128;
    sgemm16_kernel<<<smallBlocks, 256>>>(1, 0, W3l);
    sgemm16_kernel<<<smallBlocks, 256>>>(1, 1, W3r);
    edge_out_kernel<<<edgeBlocks, 256>>>(a3, b3, (float*)d_out);
}

// round 6
// speedup vs baseline: 1.9258x; 1.1128x over previous
#include <cuda_runtime.h>
#include <cuda_bf16.h>
#include <cstdint>

#define NNODES 50000
#define NEDGES 500000
#define ETOT   550000     // edges + self loops
#define HCDIM  128
#define OUTC   16
#define NSCANB ((NNODES + 1023) / 1024)   // 49
#define KW     64         // uint32 (bf16x2) per 128-feature row

// -------- scratch (no cudaMalloc allowed) --------
__device__ __align__(16) float g_xl[(size_t)NNODES * HCDIM];
__device__ __align__(16) float g_xr[(size_t)NNODES * HCDIM];
__device__ __align__(16) unsigned g_Ahi[2][(size_t)NNODES * KW];   // split-bf16 A, permuted
__device__ __align__(16) unsigned g_Alo[2][(size_t)NNODES * KW];
__device__ __align__(16) unsigned g_Whi[6][128 * KW];              // W^T split-bf16, permuted
__device__ __align__(16) unsigned g_Wlo[6][128 * KW];
__device__ int g_srcbuf[ETOT];
__device__ int g_seg[NNODES + 1];
__device__ int g_hist[NNODES];
__device__ int g_cursor[NNODES];
__device__ int g_bsum[64];

__device__ __forceinline__ float lrelu(float v) { return v > 0.f ? v : 0.2f * v; }
__device__ __forceinline__ float elu1(float v)  { return v > 0.f ? v : expm1f(v); }

// ---- bf16 split helpers ----
__device__ __forceinline__ unsigned bf16x2(float x, float y) {   // lo=x, hi=y
    unsigned r;
    asm("cvt.rn.bf16x2.f32 %0, %1, %2;" : "=r"(r) : "f"(y), "f"(x));
    return r;
}
__device__ __forceinline__ float bflo(unsigned u) { return __uint_as_float(u << 16); }
__device__ __forceinline__ float bfhi(unsigned u) { return __uint_as_float(u & 0xffff0000u); }

// pair index p (=k/2, 0..63) -> physical uint32 slot (pairs (k,k+8) adjacent per k16 block)
__device__ __forceinline__ int phys_pair(int p) {
    return ((p >> 3) << 3) + ((p & 3) << 1) + ((p >> 2) & 1);
}

__device__ __forceinline__ void store_split(unsigned* hiRow, unsigned* loRow,
                                            int q, float4 v) {
    int p0 = q * 2;
    int i0 = phys_pair(p0), i1 = phys_pair(p0 + 1);
    unsigned h0 = bf16x2(v.x, v.y);
    unsigned l0 = bf16x2(v.x - bflo(h0), v.y - bfhi(h0));
    unsigned h1 = bf16x2(v.z, v.w);
    unsigned l1 = bf16x2(v.z - bflo(h1), v.w - bfhi(h1));
    hiRow[i0] = h0; hiRow[i1] = h1;
    loRow[i0] = l0; loRow[i1] = l1;
}

// -------- edge preprocessing: counting sort by dst --------
__global__ void zero_hist_kernel() {
    int i = blockIdx.x * blockDim.x + threadIdx.x;
    if (i < NNODES) g_hist[i] = 0;
}

__global__ void hist_kernel(const int* __restrict__ ei) {
    int i = blockIdx.x * blockDim.x + threadIdx.x;
    if (i >= ETOT) return;
    int d = (i < NEDGES) ? ei[NEDGES + i] : (i - NEDGES);
    atomicAdd(&g_hist[d], 1);
}

__global__ void scan1_kernel() {   // NSCANB blocks x 1024
    __shared__ int ws[32];
    int t = threadIdx.x, lane = t & 31, wid = t >> 5;
    int i = blockIdx.x * 1024 + t;
    int v = (i < NNODES) ? g_hist[i] : 0;
    int x = v;
#pragma unroll
    for (int d = 1; d < 32; d <<= 1) {
        int y = __shfl_up_sync(0xffffffffu, x, d);
        if (lane >= d) x += y;
    }
    if (lane == 31) ws[wid] = x;
    __syncthreads();
    if (wid == 0) {
        int w = ws[lane];
#pragma unroll
        for (int d = 1; d < 32; d <<= 1) {
            int y = __shfl_up_sync(0xffffffffu, w, d);
            if (lane >= d) w += y;
        }
        ws[lane] = w;
    }
    __syncthreads();
    int incl = x + (wid ? ws[wid - 1] : 0);
    if (i < NNODES) g_seg[i] = incl - v;
    if (t == 1023) g_bsum[blockIdx.x] = incl;
}

__global__ void scan2_kernel() {   // 1 block x 64
    __shared__ int ws[2];
    int t = threadIdx.x, lane = t & 31, wid = t >> 5;
    int v = (t < NSCANB) ? g_bsum[t] : 0;
    int x = v;
#pragma unroll
    for (int d = 1; d < 32; d <<= 1) {
        int y = __shfl_up_sync(0xffffffffu, x, d);
        if (lane >= d) x += y;
    }
    if (lane == 31) ws[wid] = x;
    __syncthreads();
    int incl = x + (wid ? ws[0] : 0);
    if (t < NSCANB) g_bsum[t] = incl - v;
}

__global__ void scan3_kernel() {
    int i = blockIdx.x * blockDim.x + threadIdx.x;
    if (i < NNODES) {
        int s = g_seg[i] + g_bsum[i >> 10];
        g_seg[i] = s;
        g_cursor[i] = s;
    }
    if (i == 0) g_seg[NNODES] = ETOT;
}

__global__ void scatter_kernel(const int* __restrict__ ei) {
    int i = blockIdx.x * blockDim.x + threadIdx.x;
    if (i >= ETOT) return;
    int s, d;
    if (i < NEDGES) { s = ei[i]; d = ei[NEDGES + i]; }
    else            { s = d = i - NEDGES; }
    int p = atomicAdd(&g_cursor[d], 1);
    g_srcbuf[p] = s;
}

// -------- conversions to split-bf16 permuted layout --------
__global__ void convert_x_kernel(const float* __restrict__ x) {
    int tid = blockIdx.x * blockDim.x + threadIdx.x;
    if (tid >= NNODES * 32) return;
    int m = tid >> 5, q = tid & 31;
    float4 v = *(const float4*)(x + (size_t)m * 128 + q * 4);
    store_split(&g_Ahi[0][(size_t)m * KW], &g_Alo[0][(size_t)m * KW], q, v);
}

__global__ void convert_w_kernel(const float* W0, const float* W1, const float* W2,
                                 const float* W3, const float* W4, const float* W5) {
    int widx = blockIdx.y;
    const float* W;
    switch (widx) {
        case 0: W = W0; break;  case 1: W = W1; break;
        case 2: W = W2; break;  case 3: W = W3; break;
        case 4: W = W4; break;  default: W = W5; break;
    }
    int idx = blockIdx.x * blockDim.x + threadIdx.x;
    if (idx >= 128 * 64) return;
    int n = idx >> 6, p = idx & 63;
    float a = W[(size_t)(2 * p) * 128 + n];
    float b = W[(size_t)(2 * p + 1) * 128 + n];
    unsigned h = bf16x2(a, b);
    unsigned l = bf16x2(a - bflo(h), b - bfhi(h));
    int dst = n * KW + phys_pair(p);
    g_Whi[widx][dst] = h;
    g_Wlo[widx][dst] = l;
}

// -------- split-bf16 MMA GEMM: [M,128] x (Wl | Wr) -> g_xl, g_xr --------
#define SASTRIDE 24
__global__ __launch_bounds__(256, 2)
void mma_gemm_kernel(int aset, int wl, int wr) {
    __shared__ unsigned sA[2][64][SASTRIDE];
    __shared__ unsigned sB[2][256][SASTRIDE];

    const unsigned* aHi = g_Ahi[aset];
    const unsigned* aLo = g_Alo[aset];

    int t = threadIdx.x;
    int warp = t >> 5, lane = t & 31;
    int mt = warp & 1, nq = warp >> 1;
    int mBase = blockIdx.x * 64;
    int r = lane >> 2, c = lane & 3;

    float acc[2][8][4];
#pragma unroll
    for (int i = 0; i < 2; i++)
#pragma unroll
        for (int j = 0; j < 8; j++)
#pragma unroll
            for (int k = 0; k < 4; k++) acc[i][j][k] = 0.f;

    for (int chunk = 0; chunk < 4; chunk++) {
#pragma unroll
        for (int rep = 0; rep < 2; rep++) {
            int lin = t + rep * 256;
            int split = lin >> 8;
            int q = lin & 255;
            int m = q >> 2, c4 = q & 3;
            int gm = mBase + m;
            uint4 v = make_uint4(0u, 0u, 0u, 0u);
            if (gm < NNODES) {
                const unsigned* src = (split ? aLo : aHi) + (size_t)gm * KW + chunk * 16 + c4 * 4;
                v = *(const uint4*)src;
            }
            *(uint4*)&sA[split][m][c4 * 4] = v;
        }
#pragma unroll
        for (int rep = 0; rep < 8; rep++) {
            int lin = t + rep * 256;
            int split = lin >> 10;
            int q = lin & 1023;
            int n = q >> 2, c4 = q & 3;
            const unsigned* src;
            if (n < 128) src = (split ? g_Wlo[wl] : g_Whi[wl]) + n * KW;
            else         src = (split ? g_Wlo[wr] : g_Whi[wr]) + (n - 128) * KW;
            *(uint4*)&sB[split][n][c4 * 4] = *(const uint4*)(src + chunk * 16 + c4 * 4);
        }
        __syncthreads();

#pragma unroll
        for (int ks = 0; ks < 2; ks++) {
            unsigned Ah[2][4], Al[2][4];
#pragma unroll
            for (int tile = 0; tile < 2; tile++) {
                int row0 = mt * 32 + tile * 16 + r;
                uint2 u0 = *(const uint2*)&sA[0][row0][ks * 8 + 2 * c];
                uint2 u1 = *(const uint2*)&sA[0][row0 + 8][ks * 8 + 2 * c];
                Ah[tile][0] = u0.x; Ah[tile][2] = u0.y;
                Ah[tile][1] = u1.x; Ah[tile][3] = u1.y;
                uint2 v0 = *(const uint2*)&sA[1][row0][ks * 8 + 2 * c];
                uint2 v1 = *(const uint2*)&sA[1][row0 + 8][ks * 8 + 2 * c];
                Al[tile][0] = v0.x; Al[tile][2] = v0.y;
                Al[tile][1] = v1.x; Al[tile][3] = v1.y;
            }
#pragma unroll
            for (int nt = 0; nt < 8; nt++) {
                int n = nq * 64 + nt * 8 + r;
                uint2 bh = *(const uint2*)&sB[0][n][ks * 8 + 2 * c];
                uint2 bl = *(const uint2*)&sB[1][n][ks * 8 + 2 * c];
#pragma unroll
                for (int tile = 0; tile < 2; tile++) {
                    float* cc = acc[tile][nt];
                    asm volatile(
                        "mma.sync.aligned.m16n8k16.row.col.f32.bf16.bf16.f32 "
                        "{%0,%1,%2,%3}, {%4,%5,%6,%7}, {%8,%9}, {%0,%1,%2,%3};\n"
                        : "+f"(cc[0]), "+f"(cc[1]), "+f"(cc[2]), "+f"(cc[3])
                        : "r"(Ah[tile][0]), "r"(Ah[tile][1]), "r"(Ah[tile][2]), "r"(Ah[tile][3]),
                          "r"(bh.x), "r"(bh.y));
                    asm volatile(
                        "mma.sync.aligned.m16n8k16.row.col.f32.bf16.bf16.f32 "
                        "{%0,%1,%2,%3}, {%4,%5,%6,%7}, {%8,%9}, {%0,%1,%2,%3};\n"
                        : "+f"(cc[0]), "+f"(cc[1]), "+f"(cc[2]), "+f"(cc[3])
                        : "r"(Ah[tile][0]), "r"(Ah[tile][1]), "r"(Ah[tile][2]), "r"(Ah[tile][3]),
                          "r"(bl.x), "r"(bl.y));
                    asm volatile(
                        "mma.sync.aligned.m16n8k16.row.col.f32.bf16.bf16.f32 "
                        "{%0,%1,%2,%3}, {%4,%5,%6,%7}, {%8,%9}, {%0,%1,%2,%3};\n"
                        : "+f"(cc[0]), "+f"(cc[1]), "+f"(cc[2]), "+f"(cc[3])
                        : "r"(Al[tile][0]), "r"(Al[tile][1]), "r"(Al[tile][2]), "r"(Al[tile][3]),
                          "r"(bh.x), "r"(bh.y));
                }
            }
        }
        __syncthreads();
    }

    int c2 = c * 2;
#pragma unroll
    for (int tile = 0; tile < 2; tile++) {
        int gm0 = mBase + mt * 32 + tile * 16 + r;
#pragma unroll
        for (int nt = 0; nt < 8; nt++) {
            int n = nq * 64 + nt * 8 + c2;
            float* dst = (n < 128) ? (g_xl + n) : (g_xr + n - 128);
            if (gm0 < NNODES)
                *(float2*)(dst + (size_t)gm0 * 128) = make_float2(acc[tile][nt][0], acc[tile][nt][1]);
            if (gm0 + 8 < NNODES)
                *(float2*)(dst + (size_t)(gm0 + 8) * 128) = make_float2(acc[tile][nt][2], acc[tile][nt][3]);
        }
    }
}

// -------- layer 3: fused dual small GEMM A[M,128] @ (W3l | W3r) [128,16] --------
__global__ void sgemm16_dual_kernel(int aset, const float* __restrict__ Bl,
                                    const float* __restrict__ Br) {
    __shared__ float As[16][129];
    __shared__ float Bs[2][16][20];
    const unsigned* aHi = g_Ahi[aset];
    const unsigned* aLo = g_Alo[aset];

    int t = threadIdx.x;
    int tx = t & 15, ty = t >> 4;
    int mBase = blockIdx.x * 128;

    float accl[8], accr[8];
#pragma unroll
    for (int i = 0; i < 8; i++) { accl[i] = 0.f; accr[i] = 0.f; }

    for (int kk = 0; kk < 128; kk += 16) {
        for (int i = t; i < 128 * 16; i += 256) {
            int m = i >> 4, k = i & 15;
            int gm = mBase + m;
            float val = 0.f;
            if (gm < NNODES) {
                int klog = kk + k;
                int p = klog >> 1, odd = klog & 1;
                int idx = phys_pair(p);
                unsigned h = aHi[(size_t)gm * KW + idx];
                unsigned l = aLo[(size_t)gm * KW + idx];
                val = (odd ? bfhi(h) : bflo(h)) + (odd ? bfhi(l) : bflo(l));
            }
            As[k][m] = val;
        }
        {
            int k = t >> 4, n = t & 15;
            if (t < 256) {
                Bs[0][k][n] = Bl[(size_t)(kk + k) * 16 + n];
                Bs[1][k][n] = Br[(size_t)(kk + k) * 16 + n];
            }
        }
        __syncthreads();
#pragma unroll
        for (int k = 0; k < 16; k++) {
            float bl = Bs[0][k][tx], br = Bs[1][k][tx];
#pragma unroll
            for (int i = 0; i < 8; i++) {
                float a = As[k][ty + 16 * i];
                accl[i] = fmaf(a, bl, accl[i]);
                accr[i] = fmaf(a, br, accr[i]);
            }
        }
        __syncthreads();
    }
#pragma unroll
    for (int i = 0; i < 8; i++) {
        int gm = mBase + ty + 16 * i;
        if (gm < NNODES) {
            g_xl[(size_t)gm * OUTC + tx] = accl[i];
            g_xr[(size_t)gm * OUTC + tx] = accr[i];
        }
    }
}

// -------- edge pass, layers 0-2 (fused softmax/agg/bias/BN/ELU, emits split bf16) --------
__device__ __forceinline__ void edge_step(const float4& xv, const float4& xrv,
                                          const float4& av, float w,
                                          float& acc0, float& acc1, float& acc2,
                                          float& acc3, float& den) {
    float p = lrelu(xv.x + xrv.x) * av.x + lrelu(xv.y + xrv.y) * av.y
            + lrelu(xv.z + xrv.z) * av.z + lrelu(xv.w + xrv.w) * av.w;
    p += __shfl_xor_sync(0xffffffffu, p, 1);
    p += __shfl_xor_sync(0xffffffffu, p, 2);
    float aE = w * __expf(p);
    den += aE;
    acc0 = fmaf(xv.x, aE, acc0); acc1 = fmaf(xv.y, aE, acc1);
    acc2 = fmaf(xv.z, aE, acc2); acc3 = fmaf(xv.w, aE, acc3);
}

__global__ void edge_full_kernel(const float* __restrict__ att,
                                 const float* __restrict__ bias,
                                 const float* __restrict__ bg,
                                 const float* __restrict__ bb,
                                 const float* __restrict__ bm,
                                 const float* __restrict__ bv,
                                 int oset) {
    int gw = (blockIdx.x * blockDim.x + threadIdx.x) >> 5;
    if (gw >= NNODES) return;
    int lane = threadIdx.x & 31;
    int n = gw;
    int c0 = lane * 4;

    const float4 xrv = *(const float4*)(g_xr + (size_t)n * HCDIM + c0);
    const float4 av  = *(const float4*)(att + c0);

    int beg = g_seg[n], end = g_seg[n + 1];
    float acc0 = 0.f, acc1 = 0.f, acc2 = 0.f, acc3 = 0.f, den = 0.f;

    int e = beg;
    for (; e + 4 <= end; e += 4) {
        int s0 = g_srcbuf[e + 0];
        int s1 = g_srcbuf[e + 1];
        int s2 = g_srcbuf[e + 2];
        int s3 = g_srcbuf[e + 3];
        float4 x0 = *(const float4*)(g_xl + (size_t)s0 * HCDIM + c0);
        float4 x1 = *(const float4*)(g_xl + (size_t)s1 * HCDIM + c0);
        float4 x2 = *(const float4*)(g_xl + (size_t)s2 * HCDIM + c0);
        float4 x3 = *(const float4*)(g_xl + (size_t)s3 * HCDIM + c0);
        edge_step(x0, xrv, av, 1.f, acc0, acc1, acc2, acc3, den);
        edge_step(x1, xrv, av, 1.f, acc0, acc1, acc2, acc3, den);
        edge_step(x2, xrv, av, 1.f, acc0, acc1, acc2, acc3, den);
        edge_step(x3, xrv, av, 1.f, acc0, acc1, acc2, acc3, den);
    }
    for (; e < end; e++) {
        int s0 = g_srcbuf[e];
        float4 x0 = *(const float4*)(g_xl + (size_t)s0 * HCDIM + c0);
        edge_step(x0, xrv, av, 1.f, acc0, acc1, acc2, acc3, den);
    }

    float inv = 1.f / den;
    float4 bi  = *(const float4*)(bias + c0);
    float4 gg  = *(const float4*)(bg + c0);
    float4 bev = *(const float4*)(bb + c0);
    float4 mm  = *(const float4*)(bm + c0);
    float4 vv  = *(const float4*)(bv + c0);

    float4 r;
    r.x = elu1((acc0 * inv + bi.x - mm.x) * rsqrtf(vv.x + 1e-5f) * gg.x + bev.x);
    r.y = elu1((acc1 * inv + bi.y - mm.y) * rsqrtf(vv.y + 1e-5f) * gg.y + bev.y);
    r.z = elu1((acc2 * inv + bi.z - mm.z) * rsqrtf(vv.z + 1e-5f) * gg.z + bev.z);
    r.w = elu1((acc3 * inv + bi.w - mm.w) * rsqrtf(vv.w + 1e-5f) * gg.w + bev.w);

    store_split(&g_Ahi[oset][(size_t)n * KW], &g_Alo[oset][(size_t)n * KW], lane, r);
}

// -------- edge pass, layer 3 -> d_out --------
__global__ void edge_out_kernel(const float* __restrict__ att,
                                const float* __restrict__ bias,
                                float* __restrict__ out) {
    int gw = (blockIdx.x * blockDim.x + threadIdx.x) >> 5;
    if (gw >= NNODES) return;
    int lane = threadIdx.x & 31;
    int c = lane & 15;
    int half = lane >> 4;
    int n = gw;

    float xrv = g_xr[(size_t)n * OUTC + c];
    float av  = att[c];
    int beg = g_seg[n], end = g_seg[n + 1];
    float acc = 0.f, den = 0.f;
    int iters = (end - beg + 1) >> 1;
    for (int i = 0; i < iters; i++) {
        int e = beg + 2 * i + half;
        bool valid = (e < end);
        int s = valid ? g_srcbuf[e] : g_srcbuf[beg];
        float xlv = g_xl[(size_t)s * OUTC + c];
        float p = lrelu(xlv + xrv) * av;
        p += __shfl_xor_sync(0xffffffffu, p, 1);
        p += __shfl_xor_sync(0xffffffffu, p, 2);
        p += __shfl_xor_sync(0xffffffffu, p, 4);
        p += __shfl_xor_sync(0xffffffffu, p, 8);
        float aE = valid ? __expf(p) : 0.f;
        den += aE;
        acc = fmaf(xlv, aE, acc);
    }
    acc += __shfl_xor_sync(0xffffffffu, acc, 16);
    den += __shfl_xor_sync(0xffffffffu, den, 16);
    if (half == 0) out[(size_t)n * OUTC + c] = acc / den + bias[c];
}

// -------- orchestration --------
static cudaStream_t s_side = nullptr;
static cudaEvent_t  s_evFork = nullptr, s_evJoin = nullptr;

extern "C" void kernel_launch(void* const* d_in, const int* in_sizes, int n_in,
                              void* d_out, int out_size) {
    const float* x  = (const float*)d_in[0];
    const int*   ei = (const int*)d_in[1];
    const float* W0l = (const float*)d_in[2];
    const float* W0r = (const float*)d_in[3];
    const float* a0  = (const float*)d_in[4];
    const float* b0  = (const float*)d_in[5];
    const float* W1l = (const float*)d_in[6];
    const float* W1r = (const float*)d_in[7];
    const float* a1  = (const float*)d_in[8];
    const float* b1  = (const float*)d_in[9];
    const float* W2l = (const float*)d_in[10];
    const float* W2r = (const float*)d_in[11];
    const float* a2  = (const float*)d_in[12];
    const float* b2  = (const float*)d_in[13];
    const float* W3l = (const float*)d_in[14];
    const float* W3r = (const float*)d_in[15];
    const float* a3  = (const float*)d_in[16];
    const float* b3  = (const float*)d_in[17];
    const float* g0  = (const float*)d_in[18];
    const float* be0 = (const float*)d_in[19];
    const float* m0  = (const float*)d_in[20];
    const float* v0  = (const float*)d_in[21];
    const float* g1  = (const float*)d_in[22];
    const float* be1 = (const float*)d_in[23];
    const float* m1  = (const float*)d_in[24];
    const float* v1  = (const float*)d_in[25];
    const float* g2  = (const float*)d_in[26];
    const float* be2 = (const float*)d_in[27];
    const float* m2  = (const float*)d_in[28];
    const float* v2  = (const float*)d_in[29];

    if (s_side == nullptr) {   // one-time resource creation (no device memory)
        cudaStreamCreateWithFlags(&s_side, cudaStreamNonBlocking);
        cudaEventCreateWithFlags(&s_evFork, cudaEventDisableTiming);
        cudaEventCreateWithFlags(&s_evJoin, cudaEventDisableTiming);
    }

    // ---- fork: preprocessing (counting sort) on side stream ----
    cudaEventRecord(s_evFork, 0);
    cudaStreamWaitEvent(s_side, s_evFork, 0);
    zero_hist_kernel<<<(NNODES + 255) / 256, 256, 0, s_side>>>();
    hist_kernel<<<(ETOT + 255) / 256, 256, 0, s_side>>>(ei);
    scan1_kernel<<<NSCANB, 1024, 0, s_side>>>();
    scan2_kernel<<<1, 64, 0, s_side>>>();
    scan3_kernel<<<(NNODES + 255) / 256, 256, 0, s_side>>>();
    scatter_kernel<<<(ETOT + 255) / 256, 256, 0, s_side>>>(ei);
    cudaEventRecord(s_evJoin, s_side);

    // ---- main stream: conversions + layer-0 GEMM overlap with preprocessing ----
    convert_w_kernel<<<dim3(32, 6), 256>>>(W0l, W0r, W1l, W1r, W2l, W2r);
    convert_x_kernel<<<(NNODES * 32 + 255) / 256, 256>>>(x);

    int gemmBlocks = (NNODES + 63) / 64;
    int edgeBlocks = NNODES / 8;

    mma_gemm_kernel<<<gemmBlocks, 256>>>(0, 0, 1);
    cudaStreamWaitEvent(0, s_evJoin, 0);     // join: edges ready
    edge_full_kernel<<<edgeBlocks, 256>>>(a0, b0, g0, be0, m0, v0, 1);

    mma_gemm_kernel<<<gemmBlocks, 256>>>(1, 2, 3);
    edge_full_kernel<<<edgeBlocks, 256>>>(a1, b1, g1, be1, m1, v1, 0);

    mma_gemm_kernel<<<gemmBlocks, 256>>>(0, 4, 5);
    edge_full_kernel<<<edgeBlocks, 256>>>(a2, b2, g2, be2, m2, v2, 1);

    int smallBlocks = (NNODES + 127) / 128;
    sgemm16_dual_kernel<<<smallBlocks, 256>>>(1, W3l, W3r);
    edge_out_kernel<<<edgeBlocks, 256>>>(a3, b3, (float*)d_out);
}

// round 7
// speedup vs baseline: 2.2059x; 1.1454x over previous
#include <cuda_runtime.h>
#include <cuda_bf16.h>
#include <cstdint>

#define NNODES 50000
#define NEDGES 500000
#define ETOT   550000     // edges + self loops
#define HCDIM  128
#define OUTC   16
#define NSCANB ((NNODES + 1023) / 1024)   // 49
#define KW     64         // uint32 (bf16x2) per 128-feature row

// -------- scratch (no cudaMalloc allowed) --------
__device__ __align__(16) float g_xl[(size_t)NNODES * HCDIM];
__device__ __align__(16) float g_xr[(size_t)NNODES * HCDIM];
__device__ __align__(16) unsigned g_Ahi[2][(size_t)NNODES * KW];   // split-bf16 A, permuted
__device__ __align__(16) unsigned g_Alo[2][(size_t)NNODES * KW];
__device__ __align__(16) unsigned g_Whi[6][128 * KW];              // W^T split-bf16, permuted
__device__ __align__(16) unsigned g_Wlo[6][128 * KW];
__device__ int g_srcbuf[ETOT];
__device__ int g_seg[NNODES + 1];
__device__ int g_hist[NNODES];
__device__ int g_cursor[NNODES];
__device__ int g_bsum[64];

__device__ __forceinline__ float lrelu(float v) { return v > 0.f ? v : 0.2f * v; }
__device__ __forceinline__ float elu1(float v)  { return v > 0.f ? v : expm1f(v); }

// ---- bf16 split helpers ----
__device__ __forceinline__ unsigned bf16x2(float x, float y) {   // lo=x, hi=y
    unsigned r;
    asm("cvt.rn.bf16x2.f32 %0, %1, %2;" : "=r"(r) : "f"(y), "f"(x));
    return r;
}
__device__ __forceinline__ float bflo(unsigned u) { return __uint_as_float(u << 16); }
__device__ __forceinline__ float bfhi(unsigned u) { return __uint_as_float(u & 0xffff0000u); }

// pair index p (=k/2, 0..63) -> physical uint32 slot
__device__ __forceinline__ int phys_pair(int p) {
    return ((p >> 3) << 3) + ((p & 3) << 1) + ((p >> 2) & 1);
}

__device__ __forceinline__ void store_split(unsigned* hiRow, unsigned* loRow,
                                            int q, float4 v) {
    int p0 = q * 2;
    int i0 = phys_pair(p0), i1 = phys_pair(p0 + 1);
    unsigned h0 = bf16x2(v.x, v.y);
    unsigned l0 = bf16x2(v.x - bflo(h0), v.y - bfhi(h0));
    unsigned h1 = bf16x2(v.z, v.w);
    unsigned l1 = bf16x2(v.z - bflo(h1), v.w - bfhi(h1));
    hiRow[i0] = h0; hiRow[i1] = h1;
    loRow[i0] = l0; loRow[i1] = l1;
}

// ---- cp.async helpers ----
__device__ __forceinline__ void cp16(uint32_t dst, const void* src, bool valid) {
    int sz = valid ? 16 : 0;
    asm volatile("cp.async.cg.shared.global [%0], [%1], 16, %2;\n"
                 :: "r"(dst), "l"(src), "r"(sz));
}
__device__ __forceinline__ void cp_commit() {
    asm volatile("cp.async.commit_group;\n" ::: "memory");
}

// -------- edge preprocessing: counting sort by dst --------
__global__ void zero_hist_kernel() {
    int i = blockIdx.x * blockDim.x + threadIdx.x;
    if (i < NNODES) g_hist[i] = 0;
}

__global__ void hist_kernel(const int* __restrict__ ei) {
    int i = blockIdx.x * blockDim.x + threadIdx.x;
    if (i >= ETOT) return;
    int d = (i < NEDGES) ? ei[NEDGES + i] : (i - NEDGES);
    atomicAdd(&g_hist[d], 1);
}

__global__ void scan1_kernel() {
    __shared__ int ws[32];
    int t = threadIdx.x, lane = t & 31, wid = t >> 5;
    int i = blockIdx.x * 1024 + t;
    int v = (i < NNODES) ? g_hist[i] : 0;
    int x = v;
#pragma unroll
    for (int d = 1; d < 32; d <<= 1) {
        int y = __shfl_up_sync(0xffffffffu, x, d);
        if (lane >= d) x += y;
    }
    if (lane == 31) ws[wid] = x;
    __syncthreads();
    if (wid == 0) {
        int w = ws[lane];
#pragma unroll
        for (int d = 1; d < 32; d <<= 1) {
            int y = __shfl_up_sync(0xffffffffu, w, d);
            if (lane >= d) w += y;
        }
        ws[lane] = w;
    }
    __syncthreads();
    int incl = x + (wid ? ws[wid - 1] : 0);
    if (i < NNODES) g_seg[i] = incl - v;
    if (t == 1023) g_bsum[blockIdx.x] = incl;
}

__global__ void scan2_kernel() {
    __shared__ int ws[2];
    int t = threadIdx.x, lane = t & 31, wid = t >> 5;
    int v = (t < NSCANB) ? g_bsum[t] : 0;
    int x = v;
#pragma unroll
    for (int d = 1; d < 32; d <<= 1) {
        int y = __shfl_up_sync(0xffffffffu, x, d);
        if (lane >= d) x += y;
    }
    if (lane == 31) ws[wid] = x;
    __syncthreads();
    int incl = x + (wid ? ws[0] : 0);
    if (t < NSCANB) g_bsum[t] = incl - v;
}

__global__ void scan3_kernel() {
    int i = blockIdx.x * blockDim.x + threadIdx.x;
    if (i < NNODES) {
        int s = g_seg[i] + g_bsum[i >> 10];
        g_seg[i] = s;
        g_cursor[i] = s;
    }
    if (i == 0) g_seg[NNODES] = ETOT;
}

__global__ void scatter_kernel(const int* __restrict__ ei) {
    int i = blockIdx.x * blockDim.x + threadIdx.x;
    if (i >= ETOT) return;
    int s, d;
    if (i < NEDGES) { s = ei[i]; d = ei[NEDGES + i]; }
    else            { s = d = i - NEDGES; }
    int p = atomicAdd(&g_cursor[d], 1);
    g_srcbuf[p] = s;
}

// -------- conversions to split-bf16 permuted layout --------
__global__ void convert_x_kernel(const float* __restrict__ x) {
    int tid = blockIdx.x * blockDim.x + threadIdx.x;
    if (tid >= NNODES * 32) return;
    int m = tid >> 5, q = tid & 31;
    float4 v = *(const float4*)(x + (size_t)m * 128 + q * 4);
    store_split(&g_Ahi[0][(size_t)m * KW], &g_Alo[0][(size_t)m * KW], q, v);
}

__global__ void convert_w_kernel(const float* W0, const float* W1, const float* W2,
                                 const float* W3, const float* W4, const float* W5) {
    int widx = blockIdx.y;
    const float* W;
    switch (widx) {
        case 0: W = W0; break;  case 1: W = W1; break;
        case 2: W = W2; break;  case 3: W = W3; break;
        case 4: W = W4; break;  default: W = W5; break;
    }
    int idx = blockIdx.x * blockDim.x + threadIdx.x;
    if (idx >= 128 * 64) return;
    int n = idx >> 6, p = idx & 63;
    float a = W[(size_t)(2 * p) * 128 + n];
    float b = W[(size_t)(2 * p + 1) * 128 + n];
    unsigned h = bf16x2(a, b);
    unsigned l = bf16x2(a - bflo(h), b - bfhi(h));
    int dst = n * KW + phys_pair(p);
    g_Whi[widx][dst] = h;
    g_Wlo[widx][dst] = l;
}

// -------- split-bf16 MMA GEMM, m128 tile + cp.async double buffer --------
// dynsmem layout (uints): A[b][s][128][24] at b*6144+s*3072, B[b][s][256][24] at 12288+b*12288+s*6144
#define DSA(b, s, m) ((b) * 6144 + (s) * 3072 + (m) * 24)
#define DSB(b, s, n) (12288 + (b) * 12288 + (s) * 6144 + (n) * 24)
#define GEMM_SMEM_BYTES (36864 * 4)

extern __shared__ __align__(16) unsigned dynsmem[];

__global__ __launch_bounds__(512, 1)
void mma_gemm_kernel(int aset, int wl, int wr) {
    const unsigned* aHi = g_Ahi[aset];
    const unsigned* aLo = g_Alo[aset];

    int t = threadIdx.x;
    int warp = t >> 5, lane = t & 31;
    int mt = warp & 3, nq = warp >> 2;
    int mBase = blockIdx.x * 128;
    int r = lane >> 2, c = lane & 3;

    uint32_t smemBase = (uint32_t)__cvta_generic_to_shared(dynsmem);

    float acc[2][8][4];
#pragma unroll
    for (int i = 0; i < 2; i++)
#pragma unroll
        for (int j = 0; j < 8; j++)
#pragma unroll
            for (int k = 0; k < 4; k++) acc[i][j][k] = 0.f;

    // ---- fill helpers (as lambdas over t) ----
    auto fillA = [&](int chunk, int b) {
#pragma unroll
        for (int rep = 0; rep < 2; rep++) {
            int lin = t + rep * 512;          // 0..1023 uint4 slots
            int split = lin >> 9;
            int q = lin & 511;
            int m = q >> 2, c4 = q & 3;
            int gm = mBase + m;
            bool valid = (gm < NNODES);
            const unsigned* src = (split ? aLo : aHi)
                + (size_t)(valid ? gm : 0) * KW + chunk * 16 + c4 * 4;
            cp16(smemBase + (DSA(b, split, m) + c4 * 4) * 4, src, valid);
        }
    };
    auto fillB = [&](int chunk, int b) {
#pragma unroll
        for (int rep = 0; rep < 4; rep++) {
            int lin = t + rep * 512;          // 0..2047 uint4 slots
            int split = lin >> 10;
            int q = lin & 1023;
            int n = q >> 2, c4 = q & 3;
            const unsigned* src;
            if (n < 128) src = (split ? g_Wlo[wl] : g_Whi[wl]) + n * KW;
            else         src = (split ? g_Wlo[wr] : g_Whi[wr]) + (n - 128) * KW;
            cp16(smemBase + (DSB(b, split, n) + c4 * 4) * 4, src + chunk * 16 + c4 * 4, true);
        }
    };

    fillA(0, 0); fillB(0, 0); cp_commit();

    int buf = 0;
#pragma unroll
    for (int chunk = 0; chunk < 4; chunk++) {
        if (chunk < 3) { fillA(chunk + 1, buf ^ 1); fillB(chunk + 1, buf ^ 1); cp_commit(); }
        if (chunk < 3) asm volatile("cp.async.wait_group 1;\n" ::: "memory");
        else           asm volatile("cp.async.wait_group 0;\n" ::: "memory");
        __syncthreads();

#pragma unroll
        for (int ks = 0; ks < 2; ks++) {
            unsigned Ah[2][4], Al[2][4];
#pragma unroll
            for (int tile = 0; tile < 2; tile++) {
                int row0 = mt * 32 + tile * 16 + r;
                uint2 u0 = *(const uint2*)&dynsmem[DSA(buf, 0, row0) + ks * 8 + 2 * c];
                uint2 u1 = *(const uint2*)&dynsmem[DSA(buf, 0, row0 + 8) + ks * 8 + 2 * c];
                Ah[tile][0] = u0.x; Ah[tile][2] = u0.y;
                Ah[tile][1] = u1.x; Ah[tile][3] = u1.y;
                uint2 v0 = *(const uint2*)&dynsmem[DSA(buf, 1, row0) + ks * 8 + 2 * c];
                uint2 v1 = *(const uint2*)&dynsmem[DSA(buf, 1, row0 + 8) + ks * 8 + 2 * c];
                Al[tile][0] = v0.x; Al[tile][2] = v0.y;
                Al[tile][1] = v1.x; Al[tile][3] = v1.y;
            }
#pragma unroll
            for (int nt = 0; nt < 8; nt++) {
                int n = nq * 64 + nt * 8 + r;
                uint2 bh = *(const uint2*)&dynsmem[DSB(buf, 0, n) + ks * 8 + 2 * c];
                uint2 bl = *(const uint2*)&dynsmem[DSB(buf, 1, n) + ks * 8 + 2 * c];
#pragma unroll
                for (int tile = 0; tile < 2; tile++) {
                    float* cc = acc[tile][nt];
                    asm volatile(
                        "mma.sync.aligned.m16n8k16.row.col.f32.bf16.bf16.f32 "
                        "{%0,%1,%2,%3}, {%4,%5,%6,%7}, {%8,%9}, {%0,%1,%2,%3};\n"
                        : "+f"(cc[0]), "+f"(cc[1]), "+f"(cc[2]), "+f"(cc[3])
                        : "r"(Ah[tile][0]), "r"(Ah[tile][1]), "r"(Ah[tile][2]), "r"(Ah[tile][3]),
                          "r"(bh.x), "r"(bh.y));
                    asm volatile(
                        "mma.sync.aligned.m16n8k16.row.col.f32.bf16.bf16.f32 "
                        "{%0,%1,%2,%3}, {%4,%5,%6,%7}, {%8,%9}, {%0,%1,%2,%3};\n"
                        : "+f"(cc[0]), "+f"(cc[1]), "+f"(cc[2]), "+f"(cc[3])
                        : "r"(Ah[tile][0]), "r"(Ah[tile][1]), "r"(Ah[tile][2]), "r"(Ah[tile][3]),
                          "r"(bl.x), "r"(bl.y));
                    asm volatile(
                        "mma.sync.aligned.m16n8k16.row.col.f32.bf16.bf16.f32 "
                        "{%0,%1,%2,%3}, {%4,%5,%6,%7}, {%8,%9}, {%0,%1,%2,%3};\n"
                        : "+f"(cc[0]), "+f"(cc[1]), "+f"(cc[2]), "+f"(cc[3])
                        : "r"(Al[tile][0]), "r"(Al[tile][1]), "r"(Al[tile][2]), "r"(Al[tile][3]),
                          "r"(bh.x), "r"(bh.y));
                }
            }
        }
        __syncthreads();
        buf ^= 1;
    }

    int c2 = c * 2;
#pragma unroll
    for (int tile = 0; tile < 2; tile++) {
        int gm0 = mBase + mt * 32 + tile * 16 + r;
#pragma unroll
        for (int nt = 0; nt < 8; nt++) {
            int n = nq * 64 + nt * 8 + c2;
            float* dst = (n < 128) ? (g_xl + n) : (g_xr + n - 128);
            if (gm0 < NNODES)
                *(float2*)(dst + (size_t)gm0 * 128) = make_float2(acc[tile][nt][0], acc[tile][nt][1]);
            if (gm0 + 8 < NNODES)
                *(float2*)(dst + (size_t)(gm0 + 8) * 128) = make_float2(acc[tile][nt][2], acc[tile][nt][3]);
        }
    }
}

// -------- layer 3: fused dual small GEMM, vectorized A load --------
__global__ void sgemm16_dual_kernel(int aset, const float* __restrict__ Bl,
                                    const float* __restrict__ Br) {
    __shared__ float As[16][129];
    __shared__ float Bs[2][16][20];
    const unsigned* aHi = g_Ahi[aset];
    const unsigned* aLo = g_Alo[aset];

    int t = threadIdx.x;
    int tx = t & 15, ty = t >> 4;
    int mBase = blockIdx.x * 128;

    float accl[8], accr[8];
#pragma unroll
    for (int i = 0; i < 8; i++) { accl[i] = 0.f; accr[i] = 0.f; }

    for (int cb = 0; cb < 8; cb++) {          // 8 k16 chunks
        // A tile: 128 rows x 2 uint4-halves; thread -> (row, half)
        {
            int m = t >> 1, h = t & 1;        // 256 threads cover all
            int gm = mBase + m;
            if (gm < NNODES) {
                uint4 vh = *(const uint4*)(aHi + (size_t)gm * KW + cb * 8 + h * 4);
                uint4 vl = *(const uint4*)(aLo + (size_t)gm * KW + cb * 8 + h * 4);
                unsigned hs[4] = {vh.x, vh.y, vh.z, vh.w};
                unsigned ls[4] = {vl.x, vl.y, vl.z, vl.w};
#pragma unroll
                for (int u = 0; u < 4; u++) {
                    int j = h * 4 + u;                     // phys slot in k16 block
                    int pl = (j & 1) * 4 + (j >> 1);       // logical pair
                    As[2 * pl][m]     = bflo(hs[u]) + bflo(ls[u]);
                    As[2 * pl + 1][m] = bfhi(hs[u]) + bfhi(ls[u]);
                }
            } else {
#pragma unroll
                for (int u = 0; u < 4; u++) {
                    int j = h * 4 + u;
                    int pl = (j & 1) * 4 + (j >> 1);
                    As[2 * pl][m] = 0.f;
                    As[2 * pl + 1][m] = 0.f;
                }
            }
        }
        {
            int k = t >> 4, n = t & 15;
            Bs[0][k][n] = Bl[(size_t)(cb * 16 + k) * 16 + n];
            Bs[1][k][n] = Br[(size_t)(cb * 16 + k) * 16 + n];
        }
        __syncthreads();
#pragma unroll
        for (int k = 0; k < 16; k++) {
            float bl = Bs[0][k][tx], br = Bs[1][k][tx];
#pragma unroll
            for (int i = 0; i < 8; i++) {
                float a = As[k][ty + 16 * i];
                accl[i] = fmaf(a, bl, accl[i]);
                accr[i] = fmaf(a, br, accr[i]);
            }
        }
        __syncthreads();
    }
#pragma unroll
    for (int i = 0; i < 8; i++) {
        int gm = mBase + ty + 16 * i;
        if (gm < NNODES) {
            g_xl[(size_t)gm * OUTC + tx] = accl[i];
            g_xr[(size_t)gm * OUTC + tx] = accr[i];
        }
    }
}

// -------- edge pass, layers 0-2 --------
__device__ __forceinline__ void edge_step(const float4& xv, const float4& xrv,
                                          const float4& av,
                                          float& acc0, float& acc1, float& acc2,
                                          float& acc3, float& den) {
    float p = lrelu(xv.x + xrv.x) * av.x + lrelu(xv.y + xrv.y) * av.y
            + lrelu(xv.z + xrv.z) * av.z + lrelu(xv.w + xrv.w) * av.w;
    p += __shfl_xor_sync(0xffffffffu, p, 1);
    p += __shfl_xor_sync(0xffffffffu, p, 2);
    float aE = __expf(p);
    den += aE;
    acc0 = fmaf(xv.x, aE, acc0); acc1 = fmaf(xv.y, aE, acc1);
    acc2 = fmaf(xv.z, aE, acc2); acc3 = fmaf(xv.w, aE, acc3);
}

__global__ void edge_full_kernel(const float* __restrict__ att,
                                 const float* __restrict__ bias,
                                 const float* __restrict__ bg,
                                 const float* __restrict__ bb,
                                 const float* __restrict__ bm,
                                 const float* __restrict__ bv,
                                 int oset) {
    int gw = (blockIdx.x * blockDim.x + threadIdx.x) >> 5;
    if (gw >= NNODES) return;
    int lane = threadIdx.x & 31;
    int n = gw;
    int c0 = lane * 4;

    const float4 xrv = *(const float4*)(g_xr + (size_t)n * HCDIM + c0);
    const float4 av  = *(const float4*)(att + c0);

    int beg = g_seg[n], end = g_seg[n + 1];
    float acc0 = 0.f, acc1 = 0.f, acc2 = 0.f, acc3 = 0.f, den = 0.f;

    int e = beg;
    for (; e + 4 <= end; e += 4) {
        int s0 = g_srcbuf[e + 0];
        int s1 = g_srcbuf[e + 1];
        int s2 = g_srcbuf[e + 2];
        int s3 = g_srcbuf[e + 3];
        float4 x0 = *(const float4*)(g_xl + (size_t)s0 * HCDIM + c0);
        float4 x1 = *(const float4*)(g_xl + (size_t)s1 * HCDIM + c0);
        float4 x2 = *(const float4*)(g_xl + (size_t)s2 * HCDIM + c0);
        float4 x3 = *(const float4*)(g_xl + (size_t)s3 * HCDIM + c0);
        edge_step(x0, xrv, av, acc0, acc1, acc2, acc3, den);
        edge_step(x1, xrv, av, acc0, acc1, acc2, acc3, den);
        edge_step(x2, xrv, av, acc0, acc1, acc2, acc3, den);
        edge_step(x3, xrv, av, acc0, acc1, acc2, acc3, den);
    }
    for (; e < end; e++) {
        int s0 = g_srcbuf[e];
        float4 x0 = *(const float4*)(g_xl + (size_t)s0 * HCDIM + c0);
        edge_step(x0, xrv, av, acc0, acc1, acc2, acc3, den);
    }

    float inv = 1.f / den;
    float4 bi  = *(const float4*)(bias + c0);
    float4 gg  = *(const float4*)(bg + c0);
    float4 bev = *(const float4*)(bb + c0);
    float4 mm  = *(const float4*)(bm + c0);
    float4 vv  = *(const float4*)(bv + c0);

    float4 r;
    r.x = elu1((acc0 * inv + bi.x - mm.x) * rsqrtf(vv.x + 1e-5f) * gg.x + bev.x);
    r.y = elu1((acc1 * inv + bi.y - mm.y) * rsqrtf(vv.y + 1e-5f) * gg.y + bev.y);
    r.z = elu1((acc2 * inv + bi.z - mm.z) * rsqrtf(vv.z + 1e-5f) * gg.z + bev.z);
    r.w = elu1((acc3 * inv + bi.w - mm.w) * rsqrtf(vv.w + 1e-5f) * gg.w + bev.w);

    store_split(&g_Ahi[oset][(size_t)n * KW], &g_Alo[oset][(size_t)n * KW], lane, r);
}

// -------- edge pass, layer 3 -> d_out --------
__global__ void edge_out_kernel(const float* __restrict__ att,
                                const float* __restrict__ bias,
                                float* __restrict__ out) {
    int gw = (blockIdx.x * blockDim.x + threadIdx.x) >> 5;
    if (gw >= NNODES) return;
    int lane = threadIdx.x & 31;
    int c = lane & 15;
    int half = lane >> 4;
    int n = gw;

    float xrv = g_xr[(size_t)n * OUTC + c];
    float av  = att[c];
    int beg = g_seg[n], end = g_seg[n + 1];
    float acc = 0.f, den = 0.f;
    int iters = (end - beg + 1) >> 1;
    for (int i = 0; i < iters; i++) {
        int e = beg + 2 * i + half;
        bool valid = (e < end);
        int s = valid ? g_srcbuf[e] : g_srcbuf[beg];
        float xlv = g_xl[(size_t)s * OUTC + c];
        float p = lrelu(xlv + xrv) * av;
        p += __shfl_xor_sync(0xffffffffu, p, 1);
        p += __shfl_xor_sync(0xffffffffu, p, 2);
        p += __shfl_xor_sync(0xffffffffu, p, 4);
        p += __shfl_xor_sync(0xffffffffu, p, 8);
        float aE = valid ? __expf(p) : 0.f;
        den += aE;
        acc = fmaf(xlv, aE, acc);
    }
    acc += __shfl_xor_sync(0xffffffffu, acc, 16);
    den += __shfl_xor_sync(0xffffffffu, den, 16);
    if (half == 0) out[(size_t)n * OUTC + c] = acc / den + bias[c];
}

// -------- orchestration --------
static cudaStream_t s_side = nullptr;
static cudaEvent_t  s_evFork = nullptr, s_evJoin = nullptr;

extern "C" void kernel_launch(void* const* d_in, const int* in_sizes, int n_in,
                              void* d_out, int out_size) {
    const float* x  = (const float*)d_in[0];
    const int*   ei = (const int*)d_in[1];
    const float* W0l = (const float*)d_in[2];
    const float* W0r = (const float*)d_in[3];
    const float* a0  = (const float*)d_in[4];
    const float* b0  = (const float*)d_in[5];
    const float* W1l = (const float*)d_in[6];
    const float* W1r = (const float*)d_in[7];
    const float* a1  = (const float*)d_in[8];
    const float* b1  = (const float*)d_in[9];
    const float* W2l = (const float*)d_in[10];
    const float* W2r = (const float*)d_in[11];
    const float* a2  = (const float*)d_in[12];
    const float* b2  = (const float*)d_in[13];
    const float* W3l = (const float*)d_in[14];
    const float* W3r = (const float*)d_in[15];
    const float* a3  = (const float*)d_in[16];
    const float* b3  = (const float*)d_in[17];
    const float* g0  = (const float*)d_in[18];
    const float* be0 = (const float*)d_in[19];
    const float* m0  = (const float*)d_in[20];
    const float* v0  = (const float*)d_in[21];
    const float* g1  = (const float*)d_in[22];
    const float* be1 = (const float*)d_in[23];
    const float* m1  = (const float*)d_in[24];
    const float* v1  = (const float*)d_in[25];
    const float* g2  = (const float*)d_in[26];
    const float* be2 = (const float*)d_in[27];
    const float* m2  = (const float*)d_in[28];
    const float* v2  = (const float*)d_in[29];

    if (s_side == nullptr) {   // one-time init (no device memory allocation)
        cudaStreamCreateWithFlags(&s_side, cudaStreamNonBlocking);
        cudaEventCreateWithFlags(&s_evFork, cudaEventDisableTiming);
        cudaEventCreateWithFlags(&s_evJoin, cudaEventDisableTiming);
        cudaFuncSetAttribute(mma_gemm_kernel,
                             cudaFuncAttributeMaxDynamicSharedMemorySize,
                             GEMM_SMEM_BYTES);
    }

    // ---- fork: preprocessing (counting sort) on side stream ----
    cudaEventRecord(s_evFork, 0);
    cudaStreamWaitEvent(s_side, s_evFork, 0);
    zero_hist_kernel<<<(NNODES + 255) / 256, 256, 0, s_side>>>();
    hist_kernel<<<(ETOT + 255) / 256, 256, 0, s_side>>>(ei);
    scan1_kernel<<<NSCANB, 1024, 0, s_side>>>();
    scan2_kernel<<<1, 64, 0, s_side>>>();
    scan3_kernel<<<(NNODES + 255) / 256, 256, 0, s_side>>>();
    scatter_kernel<<<(ETOT + 255) / 256, 256, 0, s_side>>>(ei);
    cudaEventRecord(s_evJoin, s_side);

    // ---- main stream ----
    convert_w_kernel<<<dim3(32, 6), 256>>>(W0l, W0r, W1l, W1r, W2l, W2r);
    convert_x_kernel<<<(NNODES * 32 + 255) / 256, 256>>>(x);

    int gemmBlocks = (NNODES + 127) / 128;   // 391
    int edgeBlocks = NNODES / 8;

    mma_gemm_kernel<<<gemmBlocks, 512, GEMM_SMEM_BYTES>>>(0, 0, 1);
    cudaStreamWaitEvent(0, s_evJoin, 0);
    edge_full_kernel<<<edgeBlocks, 256>>>(a0, b0, g0, be0, m0, v0, 1);

    mma_gemm_kernel<<<gemmBlocks, 512, GEMM_SMEM_BYTES>>>(1, 2, 3);
    edge_full_kernel<<<edgeBlocks, 256>>>(a1, b1, g1, be1, m1, v1, 0);

    mma_gemm_kernel<<<gemmBlocks, 512, GEMM_SMEM_BYTES>>>(0, 4, 5);
    edge_full_kernel<<<edgeBlocks, 256>>>(a2, b2, g2, be2, m2, v2, 1);

    sgemm16_dual_kernel<<<gemmBlocks, 256>>>(1, W3l, W3r);
    edge_out_kernel<<<edgeBlocks, 256>>>(a3, b3, (float*)d_out);
}